// round 3
// baseline (speedup 1.0000x reference)
#include <cuda_runtime.h>
#include <math.h>
#include <stdint.h>

// Problem constants
#define D_MODEL 1024
#define NHEAD   16
#define HDIM    64
#define BATCH   4
#define SEQ     2048
#define MTOT    (BATCH * SEQ)   // 8192

// -------- scratch (static device globals; no runtime allocation) ----------
__device__ float g_q[(size_t)BATCH * NHEAD * SEQ * HDIM];      // 32 MB
__device__ float g_k[(size_t)BATCH * NHEAD * SEQ * HDIM];      // 32 MB
__device__ float g_v[(size_t)BATCH * NHEAD * SEQ * HDIM];      // 32 MB
__device__ float g_attn[(size_t)MTOT * D_MODEL];               // 32 MB

// ===========================================================================
// Kernel 1: QKV GEMM.  C[m,n] = sum_k x[m,k] * W_qkv[n,k] + b_qkv[n]
// M=8192, N=3072, K=1024.  128x128 tiles, 256 threads, 8x8 micro-tiles.
// Epilogue scatters into g_q / g_k / g_v with layout [B,H,S,Hd].
// ===========================================================================
__global__ __launch_bounds__(256) void qkv_gemm_kernel(
    const float* __restrict__ A,      // x [8192,1024]
    const float* __restrict__ W,      // W_qkv [3072,1024]
    const float* __restrict__ bias)   // b_qkv [3072]
{
    __shared__ float As[8][132];
    __shared__ float Bs[8][132];

    const int tid = threadIdx.x;
    const int tx  = tid & 15;
    const int ty  = tid >> 4;
    const int m0  = blockIdx.y * 128;
    const int n0  = blockIdx.x * 128;

    float acc[8][8];
#pragma unroll
    for (int i = 0; i < 8; i++)
#pragma unroll
        for (int j = 0; j < 8; j++) acc[i][j] = 0.f;

    const int lrow = tid >> 1;
    const int lk   = (tid & 1) * 4;
    const float* aPtr = A + (size_t)(m0 + lrow) * D_MODEL + lk;
    const float* wPtr = W + (size_t)(n0 + lrow) * D_MODEL + lk;

    for (int k0 = 0; k0 < D_MODEL; k0 += 8) {
        __syncthreads();
        float4 a = *(const float4*)(aPtr + k0);
        float4 w = *(const float4*)(wPtr + k0);
        As[lk + 0][lrow] = a.x; As[lk + 1][lrow] = a.y;
        As[lk + 2][lrow] = a.z; As[lk + 3][lrow] = a.w;
        Bs[lk + 0][lrow] = w.x; Bs[lk + 1][lrow] = w.y;
        Bs[lk + 2][lrow] = w.z; Bs[lk + 3][lrow] = w.w;
        __syncthreads();

#pragma unroll
        for (int k = 0; k < 8; k++) {
            float4 a0 = *(const float4*)&As[k][ty * 8];
            float4 a1 = *(const float4*)&As[k][ty * 8 + 4];
            float4 b0 = *(const float4*)&Bs[k][tx * 8];
            float4 b1 = *(const float4*)&Bs[k][tx * 8 + 4];
            float ar[8] = {a0.x, a0.y, a0.z, a0.w, a1.x, a1.y, a1.z, a1.w};
            float br[8] = {b0.x, b0.y, b0.z, b0.w, b1.x, b1.y, b1.z, b1.w};
#pragma unroll
            for (int i = 0; i < 8; i++)
#pragma unroll
                for (int j = 0; j < 8; j++)
                    acc[i][j] = fmaf(ar[i], br[j], acc[i][j]);
        }
    }

    // Epilogue: bias + scatter to q/k/v [B,H,S,Hd], vectorized float4 stores.
    const int mBase = m0 + ty * 8;
    const int nBase = n0 + tx * 8;
#pragma unroll
    for (int i = 0; i < 8; i++) {
        int m  = mBase + i;
        int bq = m >> 11;        // m / SEQ
        int sq = m & 2047;       // m % SEQ
#pragma unroll
        for (int jh = 0; jh < 2; jh++) {
            int n    = nBase + jh * 4;
            int sect = n >> 10;            // 0=q, 1=k, 2=v
            int f    = n & 1023;
            int h    = f >> 6;
            int d    = f & 63;
            float* dst = (sect == 0) ? g_q : (sect == 1) ? g_k : g_v;
            float4 v;
            v.x = acc[i][jh * 4 + 0] + bias[n + 0];
            v.y = acc[i][jh * 4 + 1] + bias[n + 1];
            v.z = acc[i][jh * 4 + 2] + bias[n + 2];
            v.w = acc[i][jh * 4 + 3] + bias[n + 3];
            *(float4*)(dst + (((size_t)bq * NHEAD + h) * SEQ + sq) * HDIM + d) = v;
        }
    }
}

// ===========================================================================
// Kernel 2: flash attention (fp32, non-causal).
// Grid (S/128, H, B), 256 threads. Q tile 128, KV tile 128, Hd = 64.
// Online softmax; output written to g_attn in [B,S,D] layout (D = h*64+d).
// ===========================================================================
#define FLASH_SMEM 167936  // Qs 33792 + Ks 33792 + Vs 32768 + Ps 67584

__global__ __launch_bounds__(256) void flash_attn_kernel()
{
    extern __shared__ char smem[];
    float (*Qs)[132] = (float (*)[132])(smem);            // [64][132] k-major
    float (*Ks)[132] = (float (*)[132])(smem + 33792);    // [64][132] k-major
    float (*Vs)[64]  = (float (*)[64])(smem + 67584);     // [128][64]
    float (*Ps)[132] = (float (*)[132])(smem + 100352);   // [128][132]

    const int tid = threadIdx.x;
    const int tx  = tid & 15;
    const int ty  = tid >> 4;
    const int qt  = blockIdx.x;
    const int h   = blockIdx.y;
    const int b   = blockIdx.z;
    const int s0  = qt * 128;

    const size_t headOff = ((size_t)b * NHEAD + h) * SEQ * HDIM;
    const float* qg = g_q + headOff + (size_t)s0 * HDIM;

    // Load Q tile transposed: Qs[d][row]
    for (int idx = tid; idx < 128 * 16; idx += 256) {
        int row = idx >> 4;
        int c4  = (idx & 15) * 4;
        float4 v = *(const float4*)(qg + row * HDIM + c4);
        Qs[c4 + 0][row] = v.x; Qs[c4 + 1][row] = v.y;
        Qs[c4 + 2][row] = v.z; Qs[c4 + 3][row] = v.w;
    }

    float o[8][4];
    float m_i[8], l_i[8];
#pragma unroll
    for (int i = 0; i < 8; i++) {
        m_i[i] = -INFINITY; l_i[i] = 0.f;
        o[i][0] = o[i][1] = o[i][2] = o[i][3] = 0.f;
    }

    for (int kt = 0; kt < SEQ / 128; kt++) {
        __syncthreads();  // prev iteration's PV reads of Vs/Ps done
        const float* kg = g_k + headOff + (size_t)kt * 128 * HDIM;
        const float* vg = g_v + headOff + (size_t)kt * 128 * HDIM;
        for (int idx = tid; idx < 128 * 16; idx += 256) {
            int row = idx >> 4;
            int c4  = (idx & 15) * 4;
            float4 kv = *(const float4*)(kg + row * HDIM + c4);
            Ks[c4 + 0][row] = kv.x; Ks[c4 + 1][row] = kv.y;
            Ks[c4 + 2][row] = kv.z; Ks[c4 + 3][row] = kv.w;
            *(float4*)&Vs[row][c4] = *(const float4*)(vg + row * HDIM + c4);
        }
        __syncthreads();

        // Scores: s[8][8] = Q_tile(128x64) @ K_tile^T(64x128), micro 8x8
        float s[8][8];
#pragma unroll
        for (int i = 0; i < 8; i++)
#pragma unroll
            for (int j = 0; j < 8; j++) s[i][j] = 0.f;

#pragma unroll 8
        for (int k = 0; k < HDIM; k++) {
            float4 qa = *(const float4*)&Qs[k][ty * 8];
            float4 qb = *(const float4*)&Qs[k][ty * 8 + 4];
            float4 ka = *(const float4*)&Ks[k][tx * 8];
            float4 kb = *(const float4*)&Ks[k][tx * 8 + 4];
            float qr[8] = {qa.x, qa.y, qa.z, qa.w, qb.x, qb.y, qb.z, qb.w};
            float kr[8] = {ka.x, ka.y, ka.z, ka.w, kb.x, kb.y, kb.z, kb.w};
#pragma unroll
            for (int i = 0; i < 8; i++)
#pragma unroll
                for (int j = 0; j < 8; j++)
                    s[i][j] = fmaf(qr[i], kr[j], s[i][j]);
        }

        // Online softmax (row stats across the 16 tx lanes of each row)
#pragma unroll
        for (int i = 0; i < 8; i++) {
#pragma unroll
            for (int j = 0; j < 8; j++) s[i][j] *= 0.125f;  // 1/sqrt(64)

            float mx = s[i][0];
#pragma unroll
            for (int j = 1; j < 8; j++) mx = fmaxf(mx, s[i][j]);
            mx = fmaxf(mx, __shfl_xor_sync(0xffffffffu, mx, 8));
            mx = fmaxf(mx, __shfl_xor_sync(0xffffffffu, mx, 4));
            mx = fmaxf(mx, __shfl_xor_sync(0xffffffffu, mx, 2));
            mx = fmaxf(mx, __shfl_xor_sync(0xffffffffu, mx, 1));

            float mnew = fmaxf(m_i[i], mx);
            float corr = __expf(m_i[i] - mnew);   // first tile: exp(-inf)=0

            float rsum = 0.f;
#pragma unroll
            for (int j = 0; j < 8; j++) {
                float p = __expf(s[i][j] - mnew);
                s[i][j] = p;
                rsum += p;
            }
            rsum += __shfl_xor_sync(0xffffffffu, rsum, 8);
            rsum += __shfl_xor_sync(0xffffffffu, rsum, 4);
            rsum += __shfl_xor_sync(0xffffffffu, rsum, 2);
            rsum += __shfl_xor_sync(0xffffffffu, rsum, 1);

            l_i[i] = l_i[i] * corr + rsum;
            m_i[i] = mnew;
            o[i][0] *= corr; o[i][1] *= corr; o[i][2] *= corr; o[i][3] *= corr;

            float4 p0 = make_float4(s[i][0], s[i][1], s[i][2], s[i][3]);
            float4 p1 = make_float4(s[i][4], s[i][5], s[i][6], s[i][7]);
            *(float4*)&Ps[ty * 8 + i][tx * 8]     = p0;
            *(float4*)&Ps[ty * 8 + i][tx * 8 + 4] = p1;
        }
        __syncthreads();

        // PV: O(128x64) += P(128x128) @ V(128x64); thread tile 8 rows x 4 cols
#pragma unroll 2
        for (int kk = 0; kk < 128; kk += 4) {
            float4 v0 = *(const float4*)&Vs[kk + 0][tx * 4];
            float4 v1 = *(const float4*)&Vs[kk + 1][tx * 4];
            float4 v2 = *(const float4*)&Vs[kk + 2][tx * 4];
            float4 v3 = *(const float4*)&Vs[kk + 3][tx * 4];
            float vr[4][4] = {{v0.x, v0.y, v0.z, v0.w},
                              {v1.x, v1.y, v1.z, v1.w},
                              {v2.x, v2.y, v2.z, v2.w},
                              {v3.x, v3.y, v3.z, v3.w}};
#pragma unroll
            for (int i = 0; i < 8; i++) {
                float4 p4 = *(const float4*)&Ps[ty * 8 + i][kk];
                float pr[4] = {p4.x, p4.y, p4.z, p4.w};
#pragma unroll
                for (int t = 0; t < 4; t++)
#pragma unroll
                    for (int j = 0; j < 4; j++)
                        o[i][j] = fmaf(pr[t], vr[t][j], o[i][j]);
            }
        }
    }

    // Normalize and write to g_attn in [B,S,D] layout
#pragma unroll
    for (int i = 0; i < 8; i++) {
        float inv = 1.0f / l_i[i];
        int srow  = s0 + ty * 8 + i;
        float4 v  = make_float4(o[i][0] * inv, o[i][1] * inv,
                                o[i][2] * inv, o[i][3] * inv);
        *(float4*)(g_attn + ((size_t)b * SEQ + srow) * D_MODEL
                   + h * HDIM + tx * 4) = v;
    }
}

// ===========================================================================
// Kernel 3: output projection.  out[m,n] = sum_k attn[m,k]*W_proj[n,k] + b[n]
// M=8192, N=1024, K=1024.
// ===========================================================================
__global__ __launch_bounds__(256) void proj_gemm_kernel(
    const float* __restrict__ W,      // W_proj [1024,1024]
    const float* __restrict__ bias,   // b_proj [1024]
    float* __restrict__ out)          // [8192,1024]
{
    __shared__ float As[8][132];
    __shared__ float Bs[8][132];

    const int tid = threadIdx.x;
    const int tx  = tid & 15;
    const int ty  = tid >> 4;
    const int m0  = blockIdx.y * 128;
    const int n0  = blockIdx.x * 128;

    float acc[8][8];
#pragma unroll
    for (int i = 0; i < 8; i++)
#pragma unroll
        for (int j = 0; j < 8; j++) acc[i][j] = 0.f;

    const int lrow = tid >> 1;
    const int lk   = (tid & 1) * 4;
    const float* aPtr = g_attn + (size_t)(m0 + lrow) * D_MODEL + lk;
    const float* wPtr = W + (size_t)(n0 + lrow) * D_MODEL + lk;

    for (int k0 = 0; k0 < D_MODEL; k0 += 8) {
        __syncthreads();
        float4 a = *(const float4*)(aPtr + k0);
        float4 w = *(const float4*)(wPtr + k0);
        As[lk + 0][lrow] = a.x; As[lk + 1][lrow] = a.y;
        As[lk + 2][lrow] = a.z; As[lk + 3][lrow] = a.w;
        Bs[lk + 0][lrow] = w.x; Bs[lk + 1][lrow] = w.y;
        Bs[lk + 2][lrow] = w.z; Bs[lk + 3][lrow] = w.w;
        __syncthreads();

#pragma unroll
        for (int k = 0; k < 8; k++) {
            float4 a0 = *(const float4*)&As[k][ty * 8];
            float4 a1 = *(const float4*)&As[k][ty * 8 + 4];
            float4 b0 = *(const float4*)&Bs[k][tx * 8];
            float4 b1 = *(const float4*)&Bs[k][tx * 8 + 4];
            float ar[8] = {a0.x, a0.y, a0.z, a0.w, a1.x, a1.y, a1.z, a1.w};
            float br[8] = {b0.x, b0.y, b0.z, b0.w, b1.x, b1.y, b1.z, b1.w};
#pragma unroll
            for (int i = 0; i < 8; i++)
#pragma unroll
                for (int j = 0; j < 8; j++)
                    acc[i][j] = fmaf(ar[i], br[j], acc[i][j]);
        }
    }

    const int mBase = m0 + ty * 8;
    const int nBase = n0 + tx * 8;
#pragma unroll
    for (int i = 0; i < 8; i++) {
        int m = mBase + i;
#pragma unroll
        for (int jh = 0; jh < 2; jh++) {
            int n = nBase + jh * 4;
            float4 v;
            v.x = acc[i][jh * 4 + 0] + bias[n + 0];
            v.y = acc[i][jh * 4 + 1] + bias[n + 1];
            v.z = acc[i][jh * 4 + 2] + bias[n + 2];
            v.w = acc[i][jh * 4 + 3] + bias[n + 3];
            *(float4*)(out + (size_t)m * D_MODEL + n) = v;
        }
    }
}

// ===========================================================================
// Launch
// ===========================================================================
extern "C" void kernel_launch(void* const* d_in, const int* in_sizes, int n_in,
                              void* d_out, int out_size)
{
    (void)in_sizes; (void)n_in; (void)out_size;
    const float* x      = (const float*)d_in[0];  // [4,2048,1024]
    const float* W_qkv  = (const float*)d_in[1];  // [3072,1024]
    const float* b_qkv  = (const float*)d_in[2];  // [3072]
    const float* W_proj = (const float*)d_in[3];  // [1024,1024]
    const float* b_proj = (const float*)d_in[4];  // [1024]
    float* out = (float*)d_out;

    // Opt-in to large dynamic smem for the flash kernel (not a stream op;
    // capture-safe, idempotent).
    cudaFuncSetAttribute(flash_attn_kernel,
                         cudaFuncAttributeMaxDynamicSharedMemorySize,
                         FLASH_SMEM);

    dim3 blk(256);
    qkv_gemm_kernel<<<dim3(3 * D_MODEL / 128, MTOT / 128), blk>>>(x, W_qkv, b_qkv);
    flash_attn_kernel<<<dim3(SEQ / 128, NHEAD, BATCH), blk, FLASH_SMEM>>>();
    proj_gemm_kernel<<<dim3(D_MODEL / 128, MTOT / 128), blk>>>(W_proj, b_proj, out);
}

// round 6
// speedup vs baseline: 2.3956x; 2.3956x over previous
#include <cuda_runtime.h>
#include <cuda_bf16.h>
#include <math.h>
#include <stdint.h>

// Problem constants
#define D_MODEL 1024
#define NHEAD   16
#define HDIM    64
#define BATCH   4
#define SEQ     2048
#define MTOT    (BATCH * SEQ)   // 8192
#define KD      1024

// -------- bf16 hi/lo scratch (static device globals; no allocation) --------
__device__ __nv_bfloat16 g_xh[(size_t)MTOT * KD];
__device__ __nv_bfloat16 g_xl[(size_t)MTOT * KD];
__device__ __nv_bfloat16 g_wqh[(size_t)3 * D_MODEL * KD];
__device__ __nv_bfloat16 g_wql[(size_t)3 * D_MODEL * KD];
__device__ __nv_bfloat16 g_wph[(size_t)D_MODEL * KD];
__device__ __nv_bfloat16 g_wpl[(size_t)D_MODEL * KD];
__device__ __nv_bfloat16 g_qh[(size_t)BATCH * NHEAD * SEQ * HDIM]; // [B,H,S,64]
__device__ __nv_bfloat16 g_ql[(size_t)BATCH * NHEAD * SEQ * HDIM];
__device__ __nv_bfloat16 g_kh[(size_t)BATCH * NHEAD * SEQ * HDIM];
__device__ __nv_bfloat16 g_kl[(size_t)BATCH * NHEAD * SEQ * HDIM];
__device__ __nv_bfloat16 g_vth[(size_t)BATCH * NHEAD * HDIM * SEQ]; // [B,H,64,S]
__device__ __nv_bfloat16 g_vtl[(size_t)BATCH * NHEAD * HDIM * SEQ];
__device__ __nv_bfloat16 g_ah[(size_t)MTOT * D_MODEL];               // attn hi
__device__ __nv_bfloat16 g_al[(size_t)MTOT * D_MODEL];               // attn lo

// ===========================================================================
// Helpers
// ===========================================================================
__device__ __forceinline__ uint32_t smem_u32(const void* p) {
    uint32_t a;
    asm("{ .reg .u64 t; cvta.to.shared.u64 t, %1; cvt.u32.u64 %0, t; }"
        : "=r"(a) : "l"(p));
    return a;
}
__device__ __forceinline__ void cp16(uint32_t dst, const void* src) {
    asm volatile("cp.async.cg.shared.global [%0], [%1], 16;"
                 :: "r"(dst), "l"(src));
}
#define CP_COMMIT  asm volatile("cp.async.commit_group;")
#define CP_WAIT(n) asm volatile("cp.async.wait_group %0;" :: "n"(n))

__device__ __forceinline__ void mma_bf16(float* d, const uint32_t* a,
                                         uint32_t b0, uint32_t b1) {
    asm volatile(
        "mma.sync.aligned.m16n8k16.row.col.f32.bf16.bf16.f32 "
        "{%0,%1,%2,%3}, {%4,%5,%6,%7}, {%8,%9}, {%0,%1,%2,%3};"
        : "+f"(d[0]), "+f"(d[1]), "+f"(d[2]), "+f"(d[3])
        : "r"(a[0]), "r"(a[1]), "r"(a[2]), "r"(a[3]), "r"(b0), "r"(b1));
}

__device__ __forceinline__ uint32_t pack_bf(__nv_bfloat16 a, __nv_bfloat16 b) {
    __nv_bfloat162 t; t.x = a; t.y = b;
    return *reinterpret_cast<uint32_t*>(&t);
}
__device__ __forceinline__ void split2(float v, __nv_bfloat16& h, __nv_bfloat16& l) {
    h = __float2bfloat16(v);
    l = __float2bfloat16(v - __bfloat162float(h));
}
__device__ __forceinline__ uint32_t lds32(const char* base, uint32_t off) {
    return *reinterpret_cast<const uint32_t*>(base + off);
}

// ===========================================================================
// Pre-split: fp32 -> bf16 hi + bf16 lo
// ===========================================================================
__global__ __launch_bounds__(256) void split_kernel(
    const float* __restrict__ src, __nv_bfloat16* __restrict__ hi,
    __nv_bfloat16* __restrict__ lo, int n4)
{
    int i = blockIdx.x * 256 + threadIdx.x;
    if (i >= n4) return;
    float4 v = reinterpret_cast<const float4*>(src)[i];
    __nv_bfloat16 h0, h1, h2, h3, l0, l1, l2, l3;
    split2(v.x, h0, l0); split2(v.y, h1, l1);
    split2(v.z, h2, l2); split2(v.w, h3, l3);
    reinterpret_cast<uint2*>(hi)[i] = make_uint2(pack_bf(h0, h1), pack_bf(h2, h3));
    reinterpret_cast<uint2*>(lo)[i] = make_uint2(pack_bf(l0, l1), pack_bf(l2, l3));
}

// ===========================================================================
// HMMA GEMM: C[m,n] = sum_k A[m,k]*W[n,k] (+bias), bf16x3 split.
// CTA tile 128x128, BK=32, cp.async double buffer.
// 8 warps: wm = wid&3 (m 32), wn = wid>>2 (n 64). Warp tile 32x64.
// mode 0: epilogue scatter q/k (bf16 h/l) + v transposed (bf16 h/l).
// mode 1: fp32 + bias -> Cout row-major.
// Smem per buffer: 4 arrays x [128][40] bf16 (rows padded 64B->80B).
// ===========================================================================
#define GARR 10240            // 128*40*2 bytes
#define GBUF 40960            // 4 arrays
#define GEMM_SMEM 81920

__global__ __launch_bounds__(256, 1) void gemm_hmma_kernel(
    const __nv_bfloat16* __restrict__ Ah, const __nv_bfloat16* __restrict__ Al,
    const __nv_bfloat16* __restrict__ Wh, const __nv_bfloat16* __restrict__ Wl,
    const float* __restrict__ bias, float* __restrict__ Cout, int mode)
{
    extern __shared__ char gsm[];
    const uint32_t smb = smem_u32(gsm);

    const int tid  = threadIdx.x;
    const int lane = tid & 31;
    const int wid  = tid >> 5;
    const int wm   = wid & 3;
    const int wn   = wid >> 2;
    const int g    = lane >> 2;
    const int tg   = lane & 3;
    const int m0   = blockIdx.y * 128;
    const int n0   = blockIdx.x * 128;

    const int fr = tid >> 2;          // 0..63
    const int fc = tid & 3;           // chunk 0..3 (16B each)

    // fill buffer `buf` with k-chunk c
    auto fill = [&](int buf, int c) {
        const __nv_bfloat16* sA_h = Ah + (size_t)m0 * KD + c * 32;
        const __nv_bfloat16* sA_l = Al + (size_t)m0 * KD + c * 32;
        const __nv_bfloat16* sW_h = Wh + (size_t)n0 * KD + c * 32;
        const __nv_bfloat16* sW_l = Wl + (size_t)n0 * KD + c * 32;
        const uint32_t db = smb + buf * GBUF;
        const uint32_t doff0 = (uint32_t)fr * 80 + fc * 16;
        const uint32_t doff1 = (uint32_t)(fr + 64) * 80 + fc * 16;
        const size_t soff0 = (size_t)fr * KD + fc * 8;
        const size_t soff1 = (size_t)(fr + 64) * KD + fc * 8;
        cp16(db + 0 * GARR + doff0, sA_h + soff0);
        cp16(db + 0 * GARR + doff1, sA_h + soff1);
        cp16(db + 1 * GARR + doff0, sA_l + soff0);
        cp16(db + 1 * GARR + doff1, sA_l + soff1);
        cp16(db + 2 * GARR + doff0, sW_h + soff0);
        cp16(db + 2 * GARR + doff1, sW_h + soff1);
        cp16(db + 3 * GARR + doff0, sW_l + soff0);
        cp16(db + 3 * GARR + doff1, sW_l + soff1);
    };

    float acc[2][8][4];
#pragma unroll
    for (int i = 0; i < 2; i++)
#pragma unroll
        for (int j = 0; j < 8; j++)
#pragma unroll
            for (int t = 0; t < 4; t++) acc[i][j][t] = 0.f;

    fill(0, 0);
    CP_COMMIT;

    for (int c = 0; c < KD / 32; c++) {
        const int buf = c & 1;
        if (c + 1 < KD / 32) {
            fill(buf ^ 1, c + 1);
            CP_COMMIT;
            CP_WAIT(1);
        } else {
            CP_WAIT(0);
        }
        __syncthreads();

        const char* bA_h = gsm + buf * GBUF;
        const char* bA_l = bA_h + GARR;
        const char* bW_h = bA_h + 2 * GARR;
        const char* bW_l = bA_h + 3 * GARR;

#pragma unroll
        for (int ks = 0; ks < 2; ks++) {
            uint32_t afh[2][4], afl[2][4];
#pragma unroll
            for (int mf = 0; mf < 2; mf++) {
                const uint32_t base =
                    (uint32_t)(wm * 32 + mf * 16 + g) * 80 + ks * 32 + tg * 4;
                afh[mf][0] = lds32(bA_h, base);
                afh[mf][1] = lds32(bA_h, base + 640);
                afh[mf][2] = lds32(bA_h, base + 16);
                afh[mf][3] = lds32(bA_h, base + 656);
                afl[mf][0] = lds32(bA_l, base);
                afl[mf][1] = lds32(bA_l, base + 640);
                afl[mf][2] = lds32(bA_l, base + 16);
                afl[mf][3] = lds32(bA_l, base + 656);
            }
#pragma unroll
            for (int nf = 0; nf < 8; nf++) {
                const uint32_t bb =
                    (uint32_t)(wn * 64 + nf * 8 + g) * 80 + ks * 32 + tg * 4;
                const uint32_t bh0 = lds32(bW_h, bb);
                const uint32_t bh1 = lds32(bW_h, bb + 16);
                const uint32_t bl0 = lds32(bW_l, bb);
                const uint32_t bl1 = lds32(bW_l, bb + 16);
#pragma unroll
                for (int mf = 0; mf < 2; mf++) {
                    mma_bf16(acc[mf][nf], afh[mf], bh0, bh1);
                    mma_bf16(acc[mf][nf], afl[mf], bh0, bh1);
                    mma_bf16(acc[mf][nf], afh[mf], bl0, bl1);
                }
            }
        }
        __syncthreads();
    }

    // ---------------- epilogue ----------------
    const int sect = n0 >> 10;       // 0=q 1=k 2=v (mode 0)
#pragma unroll
    for (int mf = 0; mf < 2; mf++) {
        const int m = m0 + wm * 32 + mf * 16 + g;     // rows m, m+8
#pragma unroll
        for (int nf = 0; nf < 8; nf++) {
            const int n = n0 + wn * 64 + nf * 8 + 2 * tg;
            const float2 bv = *reinterpret_cast<const float2*>(bias + n);
            const float v0 = acc[mf][nf][0] + bv.x;
            const float v1 = acc[mf][nf][1] + bv.y;
            const float v2 = acc[mf][nf][2] + bv.x;
            const float v3 = acc[mf][nf][3] + bv.y;
            if (mode == 1) {
                *reinterpret_cast<float2*>(Cout + (size_t)m * D_MODEL + n) =
                    make_float2(v0, v1);
                *reinterpret_cast<float2*>(Cout + (size_t)(m + 8) * D_MODEL + n) =
                    make_float2(v2, v3);
            } else {
                const int b = m >> 11;
                const int s = m & 2047;
                const int f = n & 1023;
                const int h = f >> 6;
                const int d = f & 63;
                __nv_bfloat16 h0, h1, h2, h3, l0, l1, l2, l3;
                split2(v0, h0, l0); split2(v1, h1, l1);
                split2(v2, h2, l2); split2(v3, h3, l3);
                if (sect == 0 || sect == 1) {
                    __nv_bfloat16* dh = (sect == 0) ? g_qh : g_kh;
                    __nv_bfloat16* dl = (sect == 0) ? g_ql : g_kl;
                    const size_t o =
                        (((size_t)b * NHEAD + h) * SEQ + s) * HDIM + d;
                    *reinterpret_cast<uint32_t*>(dh + o) = pack_bf(h0, h1);
                    *reinterpret_cast<uint32_t*>(dl + o) = pack_bf(l0, l1);
                    *reinterpret_cast<uint32_t*>(dh + o + 8 * HDIM) = pack_bf(h2, h3);
                    *reinterpret_cast<uint32_t*>(dl + o + 8 * HDIM) = pack_bf(l2, l3);
                } else {
                    const size_t o =
                        (((size_t)b * NHEAD + h) * HDIM + d) * SEQ + s;
                    g_vth[o]            = h0; g_vtl[o]            = l0;
                    g_vth[o + SEQ]      = h1; g_vtl[o + SEQ]      = l1;
                    g_vth[o + 8]        = h2; g_vtl[o + 8]        = l2;
                    g_vth[o + SEQ + 8]  = h3; g_vtl[o + SEQ + 8]  = l3;
                }
            }
        }
    }
}

// ===========================================================================
// Flash attention via HMMA (bf16x3 split), FA2 register-resident P.
// Grid (S/128, H, B), 256 thr = 8 warps, each warp owns 16 q rows x 128 kv.
// Smem: Kh/Kl [128 rows x 144B], Vth/Vtl [64 rows x 272B] (single buffer).
// ===========================================================================
#define FKH 0
#define FKL 18432
#define FVH 36864
#define FVL 54272
#define FLASH_SMEM 71680

__global__ __launch_bounds__(256, 1) void flash_hmma_kernel()
{
    extern __shared__ char fsm[];
    const uint32_t smb = smem_u32(fsm);

    const int tid  = threadIdx.x;
    const int lane = tid & 31;
    const int wid  = tid >> 5;
    const int g    = lane >> 2;
    const int tg   = lane & 3;
    const int qt   = blockIdx.x;
    const int h    = blockIdx.y;
    const int b    = blockIdx.z;
    const int s0   = qt * 128;

    const size_t khead = ((size_t)b * NHEAD + h) * SEQ * HDIM;
    const size_t vhead = ((size_t)b * NHEAD + h) * HDIM * SEQ;

    // ---- Q fragments (persistent): rows s0+wid*16+g / +8, k = hd ----
    uint32_t qfh[4][4], qfl[4][4];
    {
        const size_t r0 = khead + (size_t)(s0 + wid * 16 + g) * HDIM;
        const size_t r1 = r0 + 8 * HDIM;
#pragma unroll
        for (int ks = 0; ks < 4; ks++) {
            const int kc = ks * 16 + 2 * tg;
            qfh[ks][0] = *reinterpret_cast<const uint32_t*>(g_qh + r0 + kc);
            qfh[ks][1] = *reinterpret_cast<const uint32_t*>(g_qh + r1 + kc);
            qfh[ks][2] = *reinterpret_cast<const uint32_t*>(g_qh + r0 + kc + 8);
            qfh[ks][3] = *reinterpret_cast<const uint32_t*>(g_qh + r1 + kc + 8);
            qfl[ks][0] = *reinterpret_cast<const uint32_t*>(g_ql + r0 + kc);
            qfl[ks][1] = *reinterpret_cast<const uint32_t*>(g_ql + r1 + kc);
            qfl[ks][2] = *reinterpret_cast<const uint32_t*>(g_ql + r0 + kc + 8);
            qfl[ks][3] = *reinterpret_cast<const uint32_t*>(g_ql + r1 + kc + 8);
        }
    }

    float o[8][4];
    float mi[2] = {-INFINITY, -INFINITY};
    float li[2] = {0.f, 0.f};
#pragma unroll
    for (int nf = 0; nf < 8; nf++)
#pragma unroll
        for (int t = 0; t < 4; t++) o[nf][t] = 0.f;

    const int rk  = tid >> 3;       // 0..31 (K rows)
    const int chk = tid & 7;        // 16B chunk (K rows: 128B)
    const int rv  = tid >> 4;       // 0..15 (V rows)
    const int chv = tid & 15;       // 16B chunk (V rows: 256B)

    for (int kt = 0; kt < SEQ / 128; kt++) {
        __syncthreads();   // previous compute done before overwriting smem
        {
            const __nv_bfloat16* ksh = g_kh + khead + (size_t)(kt * 128) * HDIM;
            const __nv_bfloat16* ksl = g_kl + khead + (size_t)(kt * 128) * HDIM;
            const __nv_bfloat16* vsh = g_vth + vhead + kt * 128;
            const __nv_bfloat16* vsl = g_vtl + vhead + kt * 128;
#pragma unroll
            for (int j = 0; j < 4; j++) {
                const int r = rk + 32 * j;          // 0..127
                cp16(smb + FKH + (uint32_t)r * 144 + chk * 16,
                     ksh + (size_t)r * HDIM + chk * 8);
                cp16(smb + FKL + (uint32_t)r * 144 + chk * 16,
                     ksl + (size_t)r * HDIM + chk * 8);
            }
            // V: 64 rows x 256 bytes -> 16 chunks per row (FIXED coverage)
#pragma unroll
            for (int j = 0; j < 4; j++) {
                const int r = rv + 16 * j;          // 0..63
                cp16(smb + FVH + (uint32_t)r * 272 + chv * 16,
                     vsh + (size_t)r * SEQ + chv * 8);
                cp16(smb + FVL + (uint32_t)r * 272 + chv * 16,
                     vsl + (size_t)r * SEQ + chv * 8);
            }
        }
        CP_COMMIT;
        CP_WAIT(0);
        __syncthreads();

        // ---- scores: 16 x 128, per-thread 16 n-frags x 4 ----
        float sc[16][4];
#pragma unroll
        for (int nf = 0; nf < 16; nf++)
#pragma unroll
            for (int t = 0; t < 4; t++) sc[nf][t] = 0.f;

#pragma unroll
        for (int ks = 0; ks < 4; ks++) {
#pragma unroll
            for (int nf = 0; nf < 16; nf++) {
                const uint32_t bb = (uint32_t)(nf * 8 + g) * 144 + ks * 32 + tg * 4;
                const uint32_t bh0 = lds32(fsm + FKH, bb);
                const uint32_t bh1 = lds32(fsm + FKH, bb + 16);
                const uint32_t bl0 = lds32(fsm + FKL, bb);
                const uint32_t bl1 = lds32(fsm + FKL, bb + 16);
                mma_bf16(sc[nf], qfh[ks], bh0, bh1);
                mma_bf16(sc[nf], qfl[ks], bh0, bh1);
                mma_bf16(sc[nf], qfh[ks], bl0, bl1);
            }
        }

        // ---- online softmax ----
        float rmax[2] = {-INFINITY, -INFINITY};
#pragma unroll
        for (int nf = 0; nf < 16; nf++) {
#pragma unroll
            for (int t = 0; t < 4; t++) sc[nf][t] *= 0.125f;
            rmax[0] = fmaxf(rmax[0], fmaxf(sc[nf][0], sc[nf][1]));
            rmax[1] = fmaxf(rmax[1], fmaxf(sc[nf][2], sc[nf][3]));
        }
#pragma unroll
        for (int r = 0; r < 2; r++) {
            rmax[r] = fmaxf(rmax[r], __shfl_xor_sync(0xffffffffu, rmax[r], 1));
            rmax[r] = fmaxf(rmax[r], __shfl_xor_sync(0xffffffffu, rmax[r], 2));
        }
        float mnew[2], corr[2];
#pragma unroll
        for (int r = 0; r < 2; r++) {
            mnew[r] = fmaxf(mi[r], rmax[r]);
            corr[r] = __expf(mi[r] - mnew[r]);
            mi[r] = mnew[r];
        }
#pragma unroll
        for (int nf = 0; nf < 8; nf++) {
            o[nf][0] *= corr[0]; o[nf][1] *= corr[0];
            o[nf][2] *= corr[1]; o[nf][3] *= corr[1];
        }

        float rsum[2] = {0.f, 0.f};
        // ---- P (registers) + PV, per k16 step kk ----
#pragma unroll
        for (int kk = 0; kk < 8; kk++) {
            uint32_t pfh[4], pfl[4];
#pragma unroll
            for (int half = 0; half < 2; half++) {
                const int nf = 2 * kk + half;
                const float p0 = __expf(sc[nf][0] - mnew[0]);
                const float p1 = __expf(sc[nf][1] - mnew[0]);
                const float p2 = __expf(sc[nf][2] - mnew[1]);
                const float p3 = __expf(sc[nf][3] - mnew[1]);
                rsum[0] += p0 + p1;
                rsum[1] += p2 + p3;
                __nv_bfloat16 h0, h1, h2, h3, l0, l1, l2, l3;
                split2(p0, h0, l0); split2(p1, h1, l1);
                split2(p2, h2, l2); split2(p3, h3, l3);
                pfh[0 + 2 * half] = pack_bf(h0, h1);
                pfh[1 + 2 * half] = pack_bf(h2, h3);
                pfl[0 + 2 * half] = pack_bf(l0, l1);
                pfl[1 + 2 * half] = pack_bf(l2, l3);
            }
            // A-frag mapping: a0=(row g, k=kk*16+2tg), a1=(row g+8, same),
            // a2=(row g, k=kk*16+8+2tg), a3=(row g+8, same) — matches sc frags
            // nf=2kk (cols kk*16+2tg) and nf=2kk+1 (cols kk*16+8+2tg).
#pragma unroll
            for (int nf = 0; nf < 8; nf++) {
                const uint32_t vb = (uint32_t)(nf * 8 + g) * 272 + kk * 32 + tg * 4;
                const uint32_t vh0 = lds32(fsm + FVH, vb);
                const uint32_t vh1 = lds32(fsm + FVH, vb + 16);
                const uint32_t vl0 = lds32(fsm + FVL, vb);
                const uint32_t vl1 = lds32(fsm + FVL, vb + 16);
                mma_bf16(o[nf], pfh, vh0, vh1);
                mma_bf16(o[nf], pfl, vh0, vh1);
                mma_bf16(o[nf], pfh, vl0, vl1);
            }
        }
#pragma unroll
        for (int r = 0; r < 2; r++) {
            rsum[r] += __shfl_xor_sync(0xffffffffu, rsum[r], 1);
            rsum[r] += __shfl_xor_sync(0xffffffffu, rsum[r], 2);
            li[r] = li[r] * corr[r] + rsum[r];
        }
    }

    // ---- epilogue: write attn hi/lo [8192][1024] ----
    const float inv0 = 1.0f / li[0];
    const float inv1 = 1.0f / li[1];
    const int row0 = b * SEQ + s0 + wid * 16 + g;
    const int row1 = row0 + 8;
#pragma unroll
    for (int nf = 0; nf < 8; nf++) {
        const int col = h * HDIM + nf * 8 + 2 * tg;
        __nv_bfloat16 h0, h1, h2, h3, l0, l1, l2, l3;
        split2(o[nf][0] * inv0, h0, l0);
        split2(o[nf][1] * inv0, h1, l1);
        split2(o[nf][2] * inv1, h2, l2);
        split2(o[nf][3] * inv1, h3, l3);
        *reinterpret_cast<uint32_t*>(g_ah + (size_t)row0 * D_MODEL + col) = pack_bf(h0, h1);
        *reinterpret_cast<uint32_t*>(g_al + (size_t)row0 * D_MODEL + col) = pack_bf(l0, l1);
        *reinterpret_cast<uint32_t*>(g_ah + (size_t)row1 * D_MODEL + col) = pack_bf(h2, h3);
        *reinterpret_cast<uint32_t*>(g_al + (size_t)row1 * D_MODEL + col) = pack_bf(l2, l3);
    }
}

// ===========================================================================
// Launch
// ===========================================================================
extern "C" void kernel_launch(void* const* d_in, const int* in_sizes, int n_in,
                              void* d_out, int out_size)
{
    (void)in_sizes; (void)n_in; (void)out_size;
    const float* x      = (const float*)d_in[0];  // [4,2048,1024]
    const float* W_qkv  = (const float*)d_in[1];  // [3072,1024]
    const float* b_qkv  = (const float*)d_in[2];  // [3072]
    const float* W_proj = (const float*)d_in[3];  // [1024,1024]
    const float* b_proj = (const float*)d_in[4];  // [1024]
    float* out = (float*)d_out;

    cudaFuncSetAttribute(gemm_hmma_kernel,
                         cudaFuncAttributeMaxDynamicSharedMemorySize, GEMM_SMEM);
    cudaFuncSetAttribute(flash_hmma_kernel,
                         cudaFuncAttributeMaxDynamicSharedMemorySize, FLASH_SMEM);

    // resolve device-global addresses (host-side, capture-safe)
    __nv_bfloat16 *xh, *xl, *wqh, *wql, *wph, *wpl;
    cudaGetSymbolAddress((void**)&xh,  g_xh);
    cudaGetSymbolAddress((void**)&xl,  g_xl);
    cudaGetSymbolAddress((void**)&wqh, g_wqh);
    cudaGetSymbolAddress((void**)&wql, g_wql);
    cudaGetSymbolAddress((void**)&wph, g_wph);
    cudaGetSymbolAddress((void**)&wpl, g_wpl);
    __nv_bfloat16 *ah, *al;
    cudaGetSymbolAddress((void**)&ah, g_ah);
    cudaGetSymbolAddress((void**)&al, g_al);

    // 1) pre-split inputs to bf16 hi/lo
    split_kernel<<<(MTOT * KD / 4 + 255) / 256, 256>>>(x, xh, xl, MTOT * KD / 4);
    split_kernel<<<(3 * D_MODEL * KD / 4 + 255) / 256, 256>>>(W_qkv, wqh, wql,
                                                              3 * D_MODEL * KD / 4);
    split_kernel<<<(D_MODEL * KD / 4 + 255) / 256, 256>>>(W_proj, wph, wpl,
                                                          D_MODEL * KD / 4);

    // 2) QKV GEMM -> q/k bf16 h/l + v transposed bf16 h/l
    gemm_hmma_kernel<<<dim3(3 * D_MODEL / 128, MTOT / 128), 256, GEMM_SMEM>>>(
        xh, xl, wqh, wql, b_qkv, nullptr, 0);

    // 3) flash attention -> attn bf16 h/l
    flash_hmma_kernel<<<dim3(SEQ / 128, NHEAD, BATCH), 256, FLASH_SMEM>>>();

    // 4) projection -> out fp32
    gemm_hmma_kernel<<<dim3(D_MODEL / 128, MTOT / 128), 256, GEMM_SMEM>>>(
        ah, al, wph, wpl, b_proj, out, 1);
}

// round 7
// speedup vs baseline: 2.6678x; 1.1136x over previous
#include <cuda_runtime.h>
#include <cuda_bf16.h>
#include <math.h>
#include <stdint.h>

// Problem constants
#define D_MODEL 1024
#define NHEAD   16
#define HDIM    64
#define BATCH   4
#define SEQ     2048
#define MTOT    (BATCH * SEQ)   // 8192
#define KD      1024

// -------- bf16 hi/lo scratch (static device globals; no allocation) --------
__device__ __nv_bfloat16 g_xh[(size_t)MTOT * KD];
__device__ __nv_bfloat16 g_xl[(size_t)MTOT * KD];
__device__ __nv_bfloat16 g_wqh[(size_t)3 * D_MODEL * KD];
__device__ __nv_bfloat16 g_wql[(size_t)3 * D_MODEL * KD];
__device__ __nv_bfloat16 g_wph[(size_t)D_MODEL * KD];
__device__ __nv_bfloat16 g_wpl[(size_t)D_MODEL * KD];
__device__ __nv_bfloat16 g_qh[(size_t)BATCH * NHEAD * SEQ * HDIM]; // [B,H,S,64]
__device__ __nv_bfloat16 g_ql[(size_t)BATCH * NHEAD * SEQ * HDIM];
__device__ __nv_bfloat16 g_kh[(size_t)BATCH * NHEAD * SEQ * HDIM];
__device__ __nv_bfloat16 g_kl[(size_t)BATCH * NHEAD * SEQ * HDIM];
__device__ __nv_bfloat16 g_vth[(size_t)BATCH * NHEAD * HDIM * SEQ]; // [B,H,64,S]
__device__ __nv_bfloat16 g_vtl[(size_t)BATCH * NHEAD * HDIM * SEQ];
__device__ __nv_bfloat16 g_ah[(size_t)MTOT * D_MODEL];               // attn hi
__device__ __nv_bfloat16 g_al[(size_t)MTOT * D_MODEL];               // attn lo

// ===========================================================================
// Helpers
// ===========================================================================
__device__ __forceinline__ uint32_t smem_u32(const void* p) {
    uint32_t a;
    asm("{ .reg .u64 t; cvta.to.shared.u64 t, %1; cvt.u32.u64 %0, t; }"
        : "=r"(a) : "l"(p));
    return a;
}
__device__ __forceinline__ void cp16(uint32_t dst, const void* src) {
    asm volatile("cp.async.cg.shared.global [%0], [%1], 16;"
                 :: "r"(dst), "l"(src));
}
#define CP_COMMIT  asm volatile("cp.async.commit_group;")
#define CP_WAIT(n) asm volatile("cp.async.wait_group %0;" :: "n"(n))

__device__ __forceinline__ void mma_bf16(float* d, const uint32_t* a,
                                         uint32_t b0, uint32_t b1) {
    asm volatile(
        "mma.sync.aligned.m16n8k16.row.col.f32.bf16.bf16.f32 "
        "{%0,%1,%2,%3}, {%4,%5,%6,%7}, {%8,%9}, {%0,%1,%2,%3};"
        : "+f"(d[0]), "+f"(d[1]), "+f"(d[2]), "+f"(d[3])
        : "r"(a[0]), "r"(a[1]), "r"(a[2]), "r"(a[3]), "r"(b0), "r"(b1));
}

__device__ __forceinline__ uint32_t pack_bf(__nv_bfloat16 a, __nv_bfloat16 b) {
    __nv_bfloat162 t; t.x = a; t.y = b;
    return *reinterpret_cast<uint32_t*>(&t);
}
__device__ __forceinline__ void split2(float v, __nv_bfloat16& h, __nv_bfloat16& l) {
    h = __float2bfloat16(v);
    l = __float2bfloat16(v - __bfloat162float(h));
}
__device__ __forceinline__ uint32_t lds32(const char* base, uint32_t off) {
    return *reinterpret_cast<const uint32_t*>(base + off);
}

// ===========================================================================
// Pre-split: fp32 -> bf16 hi + bf16 lo
// ===========================================================================
__global__ __launch_bounds__(256) void split_kernel(
    const float* __restrict__ src, __nv_bfloat16* __restrict__ hi,
    __nv_bfloat16* __restrict__ lo, int n4)
{
    int i = blockIdx.x * 256 + threadIdx.x;
    if (i >= n4) return;
    float4 v = reinterpret_cast<const float4*>(src)[i];
    __nv_bfloat16 h0, h1, h2, h3, l0, l1, l2, l3;
    split2(v.x, h0, l0); split2(v.y, h1, l1);
    split2(v.z, h2, l2); split2(v.w, h3, l3);
    reinterpret_cast<uint2*>(hi)[i] = make_uint2(pack_bf(h0, h1), pack_bf(h2, h3));
    reinterpret_cast<uint2*>(lo)[i] = make_uint2(pack_bf(l0, l1), pack_bf(l2, l3));
}

// ===========================================================================
// HMMA GEMM: C[m,n] = sum_k A[m,k]*W[n,k] (+bias), bf16x3 split.
// CTA tile 64x128 (128 threads, 4 warps), BK=32, cp.async double buffer.
// Warps: wm = wid&1 (m 32), wn = wid>>1 (n 64). Warp tile 32x64.
// 3 CTAs/SM (smem 61440, regs ~145) -> 12 warps/SM for latency hiding.
// mode 0: epilogue scatter q/k (bf16 h/l) + v transposed (bf16 h/l).
// mode 1: fp32 + bias -> Cout row-major.
// ===========================================================================
#define GA_H 0                // A hi: 64 rows x 80B
#define GA_L 5120             // A lo
#define GB_H 10240            // B hi: 128 rows x 80B
#define GB_L 20480            // B lo
#define GBUF 30720            // per-stage stride
#define GEMM_SMEM 61440

__global__ __launch_bounds__(128, 3) void gemm_hmma_kernel(
    const __nv_bfloat16* __restrict__ Ah, const __nv_bfloat16* __restrict__ Al,
    const __nv_bfloat16* __restrict__ Wh, const __nv_bfloat16* __restrict__ Wl,
    const float* __restrict__ bias, float* __restrict__ Cout, int mode)
{
    extern __shared__ char gsm[];
    const uint32_t smb = smem_u32(gsm);

    const int tid  = threadIdx.x;
    const int lane = tid & 31;
    const int wid  = tid >> 5;
    const int wm   = wid & 1;
    const int wn   = wid >> 1;
    const int g    = lane >> 2;
    const int tg   = lane & 3;
    const int m0   = blockIdx.y * 64;
    const int n0   = blockIdx.x * 128;

    // fill buffer `buf` with k-chunk c
    auto fill = [&](int buf, int c) {
        const __nv_bfloat16* sA_h = Ah + (size_t)m0 * KD + c * 32;
        const __nv_bfloat16* sA_l = Al + (size_t)m0 * KD + c * 32;
        const __nv_bfloat16* sW_h = Wh + (size_t)n0 * KD + c * 32;
        const __nv_bfloat16* sW_l = Wl + (size_t)n0 * KD + c * 32;
        const uint32_t db = smb + buf * GBUF;
#pragma unroll
        for (int i = 0; i < 2; i++) {           // A: 64 rows x 4 chunks
            const int idx = tid + i * 128;      // 0..255
            const int row = idx >> 2;
            const int ch  = idx & 3;
            const uint32_t doff = (uint32_t)row * 80 + ch * 16;
            const size_t soff = (size_t)row * KD + ch * 8;
            cp16(db + GA_H + doff, sA_h + soff);
            cp16(db + GA_L + doff, sA_l + soff);
        }
#pragma unroll
        for (int i = 0; i < 4; i++) {           // B: 128 rows x 4 chunks
            const int idx = tid + i * 128;      // 0..511
            const int row = idx >> 2;
            const int ch  = idx & 3;
            const uint32_t doff = (uint32_t)row * 80 + ch * 16;
            const size_t soff = (size_t)row * KD + ch * 8;
            cp16(db + GB_H + doff, sW_h + soff);
            cp16(db + GB_L + doff, sW_l + soff);
        }
    };

    float acc[2][8][4];
#pragma unroll
    for (int i = 0; i < 2; i++)
#pragma unroll
        for (int j = 0; j < 8; j++)
#pragma unroll
            for (int t = 0; t < 4; t++) acc[i][j][t] = 0.f;

    fill(0, 0);
    CP_COMMIT;

    for (int c = 0; c < KD / 32; c++) {
        const int buf = c & 1;
        if (c + 1 < KD / 32) {
            fill(buf ^ 1, c + 1);
            CP_COMMIT;
            CP_WAIT(1);
        } else {
            CP_WAIT(0);
        }
        __syncthreads();

        const char* bA_h = gsm + buf * GBUF + GA_H;
        const char* bA_l = gsm + buf * GBUF + GA_L;
        const char* bW_h = gsm + buf * GBUF + GB_H;
        const char* bW_l = gsm + buf * GBUF + GB_L;

#pragma unroll
        for (int ks = 0; ks < 2; ks++) {
            uint32_t afh[2][4], afl[2][4];
#pragma unroll
            for (int mf = 0; mf < 2; mf++) {
                const uint32_t base =
                    (uint32_t)(wm * 32 + mf * 16 + g) * 80 + ks * 32 + tg * 4;
                afh[mf][0] = lds32(bA_h, base);
                afh[mf][1] = lds32(bA_h, base + 640);
                afh[mf][2] = lds32(bA_h, base + 16);
                afh[mf][3] = lds32(bA_h, base + 656);
                afl[mf][0] = lds32(bA_l, base);
                afl[mf][1] = lds32(bA_l, base + 640);
                afl[mf][2] = lds32(bA_l, base + 16);
                afl[mf][3] = lds32(bA_l, base + 656);
            }
#pragma unroll
            for (int nf = 0; nf < 8; nf++) {
                const uint32_t bb =
                    (uint32_t)(wn * 64 + nf * 8 + g) * 80 + ks * 32 + tg * 4;
                const uint32_t bh0 = lds32(bW_h, bb);
                const uint32_t bh1 = lds32(bW_h, bb + 16);
                const uint32_t bl0 = lds32(bW_l, bb);
                const uint32_t bl1 = lds32(bW_l, bb + 16);
#pragma unroll
                for (int mf = 0; mf < 2; mf++) {
                    mma_bf16(acc[mf][nf], afh[mf], bh0, bh1);
                    mma_bf16(acc[mf][nf], afl[mf], bh0, bh1);
                    mma_bf16(acc[mf][nf], afh[mf], bl0, bl1);
                }
            }
        }
        __syncthreads();
    }

    // ---------------- epilogue ----------------
    const int sect = n0 >> 10;       // 0=q 1=k 2=v (mode 0)
#pragma unroll
    for (int mf = 0; mf < 2; mf++) {
        const int m = m0 + wm * 32 + mf * 16 + g;     // rows m, m+8
#pragma unroll
        for (int nf = 0; nf < 8; nf++) {
            const int n = n0 + wn * 64 + nf * 8 + 2 * tg;
            const float2 bv = *reinterpret_cast<const float2*>(bias + n);
            const float v0 = acc[mf][nf][0] + bv.x;
            const float v1 = acc[mf][nf][1] + bv.y;
            const float v2 = acc[mf][nf][2] + bv.x;
            const float v3 = acc[mf][nf][3] + bv.y;
            if (mode == 1) {
                *reinterpret_cast<float2*>(Cout + (size_t)m * D_MODEL + n) =
                    make_float2(v0, v1);
                *reinterpret_cast<float2*>(Cout + (size_t)(m + 8) * D_MODEL + n) =
                    make_float2(v2, v3);
            } else {
                const int b = m >> 11;
                const int s = m & 2047;
                const int f = n & 1023;
                const int h = f >> 6;
                const int d = f & 63;
                __nv_bfloat16 h0, h1, h2, h3, l0, l1, l2, l3;
                split2(v0, h0, l0); split2(v1, h1, l1);
                split2(v2, h2, l2); split2(v3, h3, l3);
                if (sect == 0 || sect == 1) {
                    __nv_bfloat16* dh = (sect == 0) ? g_qh : g_kh;
                    __nv_bfloat16* dl = (sect == 0) ? g_ql : g_kl;
                    const size_t o =
                        (((size_t)b * NHEAD + h) * SEQ + s) * HDIM + d;
                    *reinterpret_cast<uint32_t*>(dh + o) = pack_bf(h0, h1);
                    *reinterpret_cast<uint32_t*>(dl + o) = pack_bf(l0, l1);
                    *reinterpret_cast<uint32_t*>(dh + o + 8 * HDIM) = pack_bf(h2, h3);
                    *reinterpret_cast<uint32_t*>(dl + o + 8 * HDIM) = pack_bf(l2, l3);
                } else {
                    const size_t o =
                        (((size_t)b * NHEAD + h) * HDIM + d) * SEQ + s;
                    g_vth[o]            = h0; g_vtl[o]            = l0;
                    g_vth[o + SEQ]      = h1; g_vtl[o + SEQ]      = l1;
                    g_vth[o + 8]        = h2; g_vtl[o + 8]        = l2;
                    g_vth[o + SEQ + 8]  = h3; g_vtl[o + SEQ + 8]  = l3;
                }
            }
        }
    }
}

// ===========================================================================
// Flash attention via HMMA (bf16x3 split), FA2 register-resident P.
// Grid (S/128, H, B), 256 thr = 8 warps, each warp owns 16 q rows x 128 kv.
// KV tiles double-buffered with cp.async (prefetch kt+1 during compute kt).
// Per stage: Kh/Kl [128 rows x 144B], Vth/Vtl [64 rows x 272B].
// ===========================================================================
#define FKH 0
#define FKL 18432
#define FVH 36864
#define FVL 54272
#define FST 71680               // stage stride
#define FLASH_SMEM 143360       // 2 stages

__global__ __launch_bounds__(256, 1) void flash_hmma_kernel()
{
    extern __shared__ char fsm[];
    const uint32_t smb = smem_u32(fsm);

    const int tid  = threadIdx.x;
    const int lane = tid & 31;
    const int wid  = tid >> 5;
    const int g    = lane >> 2;
    const int tg   = lane & 3;
    const int qt   = blockIdx.x;
    const int h    = blockIdx.y;
    const int b    = blockIdx.z;
    const int s0   = qt * 128;

    const size_t khead = ((size_t)b * NHEAD + h) * SEQ * HDIM;
    const size_t vhead = ((size_t)b * NHEAD + h) * HDIM * SEQ;

    const int rk  = tid >> 3;       // 0..31 (K rows)
    const int chk = tid & 7;        // 16B chunk (K rows: 128B)
    const int rv  = tid >> 4;       // 0..15 (V rows)
    const int chv = tid & 15;       // 16B chunk (V rows: 256B)

    // issue cp.async loads of KV tile kt into stage buf
    auto load_kv = [&](int kt, int buf) {
        const uint32_t sb = smb + buf * FST;
        const __nv_bfloat16* ksh = g_kh + khead + (size_t)(kt * 128) * HDIM;
        const __nv_bfloat16* ksl = g_kl + khead + (size_t)(kt * 128) * HDIM;
        const __nv_bfloat16* vsh = g_vth + vhead + kt * 128;
        const __nv_bfloat16* vsl = g_vtl + vhead + kt * 128;
#pragma unroll
        for (int j = 0; j < 4; j++) {
            const int r = rk + 32 * j;          // 0..127
            cp16(sb + FKH + (uint32_t)r * 144 + chk * 16,
                 ksh + (size_t)r * HDIM + chk * 8);
            cp16(sb + FKL + (uint32_t)r * 144 + chk * 16,
                 ksl + (size_t)r * HDIM + chk * 8);
        }
#pragma unroll
        for (int j = 0; j < 4; j++) {
            const int r = rv + 16 * j;          // 0..63
            cp16(sb + FVH + (uint32_t)r * 272 + chv * 16,
                 vsh + (size_t)r * SEQ + chv * 8);
            cp16(sb + FVL + (uint32_t)r * 272 + chv * 16,
                 vsl + (size_t)r * SEQ + chv * 8);
        }
    };

    // ---- Q fragments (persistent): rows s0+wid*16+g / +8, k = hd ----
    uint32_t qfh[4][4], qfl[4][4];
    {
        const size_t r0 = khead + (size_t)(s0 + wid * 16 + g) * HDIM;
        const size_t r1 = r0 + 8 * HDIM;
#pragma unroll
        for (int ks = 0; ks < 4; ks++) {
            const int kc = ks * 16 + 2 * tg;
            qfh[ks][0] = *reinterpret_cast<const uint32_t*>(g_qh + r0 + kc);
            qfh[ks][1] = *reinterpret_cast<const uint32_t*>(g_qh + r1 + kc);
            qfh[ks][2] = *reinterpret_cast<const uint32_t*>(g_qh + r0 + kc + 8);
            qfh[ks][3] = *reinterpret_cast<const uint32_t*>(g_qh + r1 + kc + 8);
            qfl[ks][0] = *reinterpret_cast<const uint32_t*>(g_ql + r0 + kc);
            qfl[ks][1] = *reinterpret_cast<const uint32_t*>(g_ql + r1 + kc);
            qfl[ks][2] = *reinterpret_cast<const uint32_t*>(g_ql + r0 + kc + 8);
            qfl[ks][3] = *reinterpret_cast<const uint32_t*>(g_ql + r1 + kc + 8);
        }
    }

    float o[8][4];
    float mi[2] = {-INFINITY, -INFINITY};
    float li[2] = {0.f, 0.f};
#pragma unroll
    for (int nf = 0; nf < 8; nf++)
#pragma unroll
        for (int t = 0; t < 4; t++) o[nf][t] = 0.f;

    load_kv(0, 0);
    CP_COMMIT;

    for (int kt = 0; kt < SEQ / 128; kt++) {
        const int buf = kt & 1;
        if (kt + 1 < SEQ / 128) {
            load_kv(kt + 1, buf ^ 1);   // prefetch next tile
            CP_COMMIT;
            CP_WAIT(1);                 // current tile resident
        } else {
            CP_WAIT(0);
        }
        __syncthreads();

        const char* pK_h = fsm + buf * FST + FKH;
        const char* pK_l = fsm + buf * FST + FKL;
        const char* pV_h = fsm + buf * FST + FVH;
        const char* pV_l = fsm + buf * FST + FVL;

        // ---- scores: 16 x 128, per-thread 16 n-frags x 4 ----
        float sc[16][4];
#pragma unroll
        for (int nf = 0; nf < 16; nf++)
#pragma unroll
            for (int t = 0; t < 4; t++) sc[nf][t] = 0.f;

#pragma unroll
        for (int ks = 0; ks < 4; ks++) {
#pragma unroll
            for (int nf = 0; nf < 16; nf++) {
                const uint32_t bb = (uint32_t)(nf * 8 + g) * 144 + ks * 32 + tg * 4;
                const uint32_t bh0 = lds32(pK_h, bb);
                const uint32_t bh1 = lds32(pK_h, bb + 16);
                const uint32_t bl0 = lds32(pK_l, bb);
                const uint32_t bl1 = lds32(pK_l, bb + 16);
                mma_bf16(sc[nf], qfh[ks], bh0, bh1);
                mma_bf16(sc[nf], qfl[ks], bh0, bh1);
                mma_bf16(sc[nf], qfh[ks], bl0, bl1);
            }
        }

        // ---- online softmax ----
        float rmax[2] = {-INFINITY, -INFINITY};
#pragma unroll
        for (int nf = 0; nf < 16; nf++) {
#pragma unroll
            for (int t = 0; t < 4; t++) sc[nf][t] *= 0.125f;
            rmax[0] = fmaxf(rmax[0], fmaxf(sc[nf][0], sc[nf][1]));
            rmax[1] = fmaxf(rmax[1], fmaxf(sc[nf][2], sc[nf][3]));
        }
#pragma unroll
        for (int r = 0; r < 2; r++) {
            rmax[r] = fmaxf(rmax[r], __shfl_xor_sync(0xffffffffu, rmax[r], 1));
            rmax[r] = fmaxf(rmax[r], __shfl_xor_sync(0xffffffffu, rmax[r], 2));
        }
        float mnew[2], corr[2];
#pragma unroll
        for (int r = 0; r < 2; r++) {
            mnew[r] = fmaxf(mi[r], rmax[r]);
            corr[r] = __expf(mi[r] - mnew[r]);
            mi[r] = mnew[r];
        }
#pragma unroll
        for (int nf = 0; nf < 8; nf++) {
            o[nf][0] *= corr[0]; o[nf][1] *= corr[0];
            o[nf][2] *= corr[1]; o[nf][3] *= corr[1];
        }

        float rsum[2] = {0.f, 0.f};
        // ---- P (registers) + PV, per k16 step kk ----
#pragma unroll
        for (int kk = 0; kk < 8; kk++) {
            uint32_t pfh[4], pfl[4];
#pragma unroll
            for (int half = 0; half < 2; half++) {
                const int nf = 2 * kk + half;
                const float p0 = __expf(sc[nf][0] - mnew[0]);
                const float p1 = __expf(sc[nf][1] - mnew[0]);
                const float p2 = __expf(sc[nf][2] - mnew[1]);
                const float p3 = __expf(sc[nf][3] - mnew[1]);
                rsum[0] += p0 + p1;
                rsum[1] += p2 + p3;
                __nv_bfloat16 h0, h1, h2, h3, l0, l1, l2, l3;
                split2(p0, h0, l0); split2(p1, h1, l1);
                split2(p2, h2, l2); split2(p3, h3, l3);
                pfh[0 + 2 * half] = pack_bf(h0, h1);
                pfh[1 + 2 * half] = pack_bf(h2, h3);
                pfl[0 + 2 * half] = pack_bf(l0, l1);
                pfl[1 + 2 * half] = pack_bf(l2, l3);
            }
#pragma unroll
            for (int nf = 0; nf < 8; nf++) {
                const uint32_t vb = (uint32_t)(nf * 8 + g) * 272 + kk * 32 + tg * 4;
                const uint32_t vh0 = lds32(pV_h, vb);
                const uint32_t vh1 = lds32(pV_h, vb + 16);
                const uint32_t vl0 = lds32(pV_l, vb);
                const uint32_t vl1 = lds32(pV_l, vb + 16);
                mma_bf16(o[nf], pfh, vh0, vh1);
                mma_bf16(o[nf], pfl, vh0, vh1);
                mma_bf16(o[nf], pfh, vl0, vl1);
            }
        }
#pragma unroll
        for (int r = 0; r < 2; r++) {
            rsum[r] += __shfl_xor_sync(0xffffffffu, rsum[r], 1);
            rsum[r] += __shfl_xor_sync(0xffffffffu, rsum[r], 2);
            li[r] = li[r] * corr[r] + rsum[r];
        }
        __syncthreads();   // all reads of buf done before kt+2 load overwrites
    }

    // ---- epilogue: write attn hi/lo [8192][1024] ----
    const float inv0 = 1.0f / li[0];
    const float inv1 = 1.0f / li[1];
    const int row0 = b * SEQ + s0 + wid * 16 + g;
    const int row1 = row0 + 8;
#pragma unroll
    for (int nf = 0; nf < 8; nf++) {
        const int col = h * HDIM + nf * 8 + 2 * tg;
        __nv_bfloat16 h0, h1, h2, h3, l0, l1, l2, l3;
        split2(o[nf][0] * inv0, h0, l0);
        split2(o[nf][1] * inv0, h1, l1);
        split2(o[nf][2] * inv1, h2, l2);
        split2(o[nf][3] * inv1, h3, l3);
        *reinterpret_cast<uint32_t*>(g_ah + (size_t)row0 * D_MODEL + col) = pack_bf(h0, h1);
        *reinterpret_cast<uint32_t*>(g_al + (size_t)row0 * D_MODEL + col) = pack_bf(l0, l1);
        *reinterpret_cast<uint32_t*>(g_ah + (size_t)row1 * D_MODEL + col) = pack_bf(h2, h3);
        *reinterpret_cast<uint32_t*>(g_al + (size_t)row1 * D_MODEL + col) = pack_bf(l2, l3);
    }
}

// ===========================================================================
// Launch
// ===========================================================================
extern "C" void kernel_launch(void* const* d_in, const int* in_sizes, int n_in,
                              void* d_out, int out_size)
{
    (void)in_sizes; (void)n_in; (void)out_size;
    const float* x      = (const float*)d_in[0];  // [4,2048,1024]
    const float* W_qkv  = (const float*)d_in[1];  // [3072,1024]
    const float* b_qkv  = (const float*)d_in[2];  // [3072]
    const float* W_proj = (const float*)d_in[3];  // [1024,1024]
    const float* b_proj = (const float*)d_in[4];  // [1024]
    float* out = (float*)d_out;

    cudaFuncSetAttribute(gemm_hmma_kernel,
                         cudaFuncAttributeMaxDynamicSharedMemorySize, GEMM_SMEM);
    cudaFuncSetAttribute(flash_hmma_kernel,
                         cudaFuncAttributeMaxDynamicSharedMemorySize, FLASH_SMEM);

    // resolve device-global addresses (host-side, capture-safe)
    __nv_bfloat16 *xh, *xl, *wqh, *wql, *wph, *wpl;
    cudaGetSymbolAddress((void**)&xh,  g_xh);
    cudaGetSymbolAddress((void**)&xl,  g_xl);
    cudaGetSymbolAddress((void**)&wqh, g_wqh);
    cudaGetSymbolAddress((void**)&wql, g_wql);
    cudaGetSymbolAddress((void**)&wph, g_wph);
    cudaGetSymbolAddress((void**)&wpl, g_wpl);
    __nv_bfloat16 *ah, *al;
    cudaGetSymbolAddress((void**)&ah, g_ah);
    cudaGetSymbolAddress((void**)&al, g_al);

    // 1) pre-split inputs to bf16 hi/lo
    split_kernel<<<(MTOT * KD / 4 + 255) / 256, 256>>>(x, xh, xl, MTOT * KD / 4);
    split_kernel<<<(3 * D_MODEL * KD / 4 + 255) / 256, 256>>>(W_qkv, wqh, wql,
                                                              3 * D_MODEL * KD / 4);
    split_kernel<<<(D_MODEL * KD / 4 + 255) / 256, 256>>>(W_proj, wph, wpl,
                                                          D_MODEL * KD / 4);

    // 2) QKV GEMM -> q/k bf16 h/l + v transposed bf16 h/l
    gemm_hmma_kernel<<<dim3(3 * D_MODEL / 128, MTOT / 64), 128, GEMM_SMEM>>>(
        xh, xl, wqh, wql, b_qkv, nullptr, 0);

    // 3) flash attention -> attn bf16 h/l
    flash_hmma_kernel<<<dim3(SEQ / 128, NHEAD, BATCH), 256, FLASH_SMEM>>>();

    // 4) projection -> out fp32
    gemm_hmma_kernel<<<dim3(D_MODEL / 128, MTOT / 64), 128, GEMM_SMEM>>>(
        ah, al, wph, wpl, b_proj, out, 1);
}

// round 8
// speedup vs baseline: 2.8467x; 1.0671x over previous
#include <cuda_runtime.h>
#include <cuda_bf16.h>
#include <math.h>
#include <stdint.h>

// Problem constants
#define D_MODEL 1024
#define NHEAD   16
#define HDIM    64
#define BATCH   4
#define SEQ     2048
#define MTOT    (BATCH * SEQ)   // 8192
#define KD      1024

// -------- bf16 hi/lo scratch (static device globals; no allocation) --------
__device__ __nv_bfloat16 g_xh[(size_t)MTOT * KD];
__device__ __nv_bfloat16 g_xl[(size_t)MTOT * KD];
__device__ __nv_bfloat16 g_wqh[(size_t)3 * D_MODEL * KD];
__device__ __nv_bfloat16 g_wql[(size_t)3 * D_MODEL * KD];
__device__ __nv_bfloat16 g_wph[(size_t)D_MODEL * KD];
__device__ __nv_bfloat16 g_wpl[(size_t)D_MODEL * KD];
__device__ __nv_bfloat16 g_qh[(size_t)BATCH * NHEAD * SEQ * HDIM]; // [B,H,S,64]
__device__ __nv_bfloat16 g_ql[(size_t)BATCH * NHEAD * SEQ * HDIM];
__device__ __nv_bfloat16 g_kh[(size_t)BATCH * NHEAD * SEQ * HDIM];
__device__ __nv_bfloat16 g_kl[(size_t)BATCH * NHEAD * SEQ * HDIM];
__device__ __nv_bfloat16 g_vth[(size_t)BATCH * NHEAD * HDIM * SEQ]; // [B,H,64,S]
__device__ __nv_bfloat16 g_vtl[(size_t)BATCH * NHEAD * HDIM * SEQ];
__device__ __nv_bfloat16 g_ah[(size_t)MTOT * D_MODEL];               // attn hi
__device__ __nv_bfloat16 g_al[(size_t)MTOT * D_MODEL];               // attn lo

// ===========================================================================
// Helpers
// ===========================================================================
__device__ __forceinline__ uint32_t smem_u32(const void* p) {
    uint32_t a;
    asm("{ .reg .u64 t; cvta.to.shared.u64 t, %1; cvt.u32.u64 %0, t; }"
        : "=r"(a) : "l"(p));
    return a;
}
__device__ __forceinline__ void cp16(uint32_t dst, const void* src) {
    asm volatile("cp.async.cg.shared.global [%0], [%1], 16;"
                 :: "r"(dst), "l"(src));
}
#define CP_COMMIT  asm volatile("cp.async.commit_group;")
#define CP_WAIT(n) asm volatile("cp.async.wait_group %0;" :: "n"(n))

__device__ __forceinline__ void mma_bf16(float* d, const uint32_t* a,
                                         uint32_t b0, uint32_t b1) {
    asm volatile(
        "mma.sync.aligned.m16n8k16.row.col.f32.bf16.bf16.f32 "
        "{%0,%1,%2,%3}, {%4,%5,%6,%7}, {%8,%9}, {%0,%1,%2,%3};"
        : "+f"(d[0]), "+f"(d[1]), "+f"(d[2]), "+f"(d[3])
        : "r"(a[0]), "r"(a[1]), "r"(a[2]), "r"(a[3]), "r"(b0), "r"(b1));
}
__device__ __forceinline__ void ldsm4(uint32_t* r, uint32_t addr) {
    asm volatile("ldmatrix.sync.aligned.m8n8.x4.shared.b16 {%0,%1,%2,%3}, [%4];"
        : "=r"(r[0]), "=r"(r[1]), "=r"(r[2]), "=r"(r[3]) : "r"(addr));
}

__device__ __forceinline__ uint32_t pack_bf(__nv_bfloat16 a, __nv_bfloat16 b) {
    __nv_bfloat162 t; t.x = a; t.y = b;
    return *reinterpret_cast<uint32_t*>(&t);
}
__device__ __forceinline__ void split2(float v, __nv_bfloat16& h, __nv_bfloat16& l) {
    h = __float2bfloat16(v);
    l = __float2bfloat16(v - __bfloat162float(h));
}

// ===========================================================================
// Pre-split: fp32 -> bf16 hi + bf16 lo
// ===========================================================================
__global__ __launch_bounds__(256) void split_kernel(
    const float* __restrict__ src, __nv_bfloat16* __restrict__ hi,
    __nv_bfloat16* __restrict__ lo, int n4)
{
    int i = blockIdx.x * 256 + threadIdx.x;
    if (i >= n4) return;
    float4 v = reinterpret_cast<const float4*>(src)[i];
    __nv_bfloat16 h0, h1, h2, h3, l0, l1, l2, l3;
    split2(v.x, h0, l0); split2(v.y, h1, l1);
    split2(v.z, h2, l2); split2(v.w, h3, l3);
    reinterpret_cast<uint2*>(hi)[i] = make_uint2(pack_bf(h0, h1), pack_bf(h2, h3));
    reinterpret_cast<uint2*>(lo)[i] = make_uint2(pack_bf(l0, l1), pack_bf(l2, l3));
}

// ===========================================================================
// HMMA GEMM: C[m,n] = sum_k A[m,k]*W[n,k] (+bias), bf16x3 split.
// CTA tile 128x128 (128 threads, 4 warps), BK=32, cp.async double buffer.
// Warps: wm = wid&1 (m 64), wn = wid>>1 (n 64). Warp tile 64x64.
// Fragments via ldmatrix.x4. 2 CTAs/SM.
// mode 0: epilogue scatter q/k (bf16 h/l) + v transposed (bf16 h/l).
// mode 1: fp32 + bias -> Cout row-major.
// ===========================================================================
#define GA_H 0                // A hi: 128 rows x 80B
#define GA_L 10240            // A lo
#define GB_H 20480            // B hi: 128 rows x 80B
#define GB_L 30720            // B lo
#define GBUF 40960            // per-stage stride
#define GEMM_SMEM 81920

__global__ __launch_bounds__(128, 2) void gemm_hmma_kernel(
    const __nv_bfloat16* __restrict__ Ah, const __nv_bfloat16* __restrict__ Al,
    const __nv_bfloat16* __restrict__ Wh, const __nv_bfloat16* __restrict__ Wl,
    const float* __restrict__ bias, float* __restrict__ Cout, int mode)
{
    extern __shared__ char gsm[];
    const uint32_t smb = smem_u32(gsm);

    const int tid  = threadIdx.x;
    const int lane = tid & 31;
    const int wid  = tid >> 5;
    const int wm   = wid & 1;
    const int wn   = wid >> 1;
    const int g    = lane >> 2;
    const int tg   = lane & 3;
    const int m0   = blockIdx.y * 128;
    const int n0   = blockIdx.x * 128;

    // ldmatrix lane-address components
    const int mrowA = (lane & 7) | (((lane >> 3) & 1) << 3);  // A: matrices 0/1 rows, 2/3 k-hi
    const int khA   = ((lane >> 4) & 1) * 16;
    const int nrowB = (lane & 7) | (((lane >> 4) & 1) << 3);  // B: matrices 0/1 k lo/hi, 2/3 rows+8
    const int khB   = ((lane >> 3) & 1) * 16;

    // fill buffer `buf` with k-chunk c (A/B: 128 rows x 64B each, hi+lo)
    auto fill = [&](int buf, int c) {
        const __nv_bfloat16* sA_h = Ah + (size_t)m0 * KD + c * 32;
        const __nv_bfloat16* sA_l = Al + (size_t)m0 * KD + c * 32;
        const __nv_bfloat16* sW_h = Wh + (size_t)n0 * KD + c * 32;
        const __nv_bfloat16* sW_l = Wl + (size_t)n0 * KD + c * 32;
        const uint32_t db = smb + buf * GBUF;
#pragma unroll
        for (int i = 0; i < 4; i++) {
            const int idx = tid + i * 128;      // 0..511
            const int row = idx >> 2;
            const int ch  = idx & 3;
            const uint32_t doff = (uint32_t)row * 80 + ch * 16;
            const size_t soff = (size_t)row * KD + ch * 8;
            cp16(db + GA_H + doff, sA_h + soff);
            cp16(db + GA_L + doff, sA_l + soff);
            cp16(db + GB_H + doff, sW_h + soff);
            cp16(db + GB_L + doff, sW_l + soff);
        }
    };

    float acc[4][8][4];
#pragma unroll
    for (int i = 0; i < 4; i++)
#pragma unroll
        for (int j = 0; j < 8; j++)
#pragma unroll
            for (int t = 0; t < 4; t++) acc[i][j][t] = 0.f;

    fill(0, 0);
    CP_COMMIT;

    for (int c = 0; c < KD / 32; c++) {
        const int buf = c & 1;
        if (c + 1 < KD / 32) {
            fill(buf ^ 1, c + 1);
            CP_COMMIT;
            CP_WAIT(1);
        } else {
            CP_WAIT(0);
        }
        __syncthreads();

        const uint32_t db = smb + buf * GBUF;

#pragma unroll
        for (int ks = 0; ks < 2; ks++) {
            uint32_t afh[4][4], afl[4][4];
#pragma unroll
            for (int mf = 0; mf < 4; mf++) {
                const uint32_t ao =
                    (uint32_t)(wm * 64 + mf * 16 + mrowA) * 80 + ks * 32 + khA;
                ldsm4(afh[mf], db + GA_H + ao);
                ldsm4(afl[mf], db + GA_L + ao);
            }
#pragma unroll
            for (int j = 0; j < 4; j++) {       // nf pair (2j, 2j+1)
                uint32_t bh[4], bl[4];
                const uint32_t bo =
                    (uint32_t)(wn * 64 + j * 16 + nrowB) * 80 + ks * 32 + khB;
                ldsm4(bh, db + GB_H + bo);
                ldsm4(bl, db + GB_L + bo);
#pragma unroll
                for (int mf = 0; mf < 4; mf++) {
                    mma_bf16(acc[mf][2 * j],     afh[mf], bh[0], bh[1]);
                    mma_bf16(acc[mf][2 * j],     afl[mf], bh[0], bh[1]);
                    mma_bf16(acc[mf][2 * j],     afh[mf], bl[0], bl[1]);
                    mma_bf16(acc[mf][2 * j + 1], afh[mf], bh[2], bh[3]);
                    mma_bf16(acc[mf][2 * j + 1], afl[mf], bh[2], bh[3]);
                    mma_bf16(acc[mf][2 * j + 1], afh[mf], bl[2], bl[3]);
                }
            }
        }
        __syncthreads();
    }

    // ---------------- epilogue ----------------
    const int sect = n0 >> 10;       // 0=q 1=k 2=v (mode 0)
#pragma unroll
    for (int mf = 0; mf < 4; mf++) {
        const int m = m0 + wm * 64 + mf * 16 + g;     // rows m, m+8
#pragma unroll
        for (int nf = 0; nf < 8; nf++) {
            const int n = n0 + wn * 64 + nf * 8 + 2 * tg;
            const float2 bv = *reinterpret_cast<const float2*>(bias + n);
            const float v0 = acc[mf][nf][0] + bv.x;
            const float v1 = acc[mf][nf][1] + bv.y;
            const float v2 = acc[mf][nf][2] + bv.x;
            const float v3 = acc[mf][nf][3] + bv.y;
            if (mode == 1) {
                *reinterpret_cast<float2*>(Cout + (size_t)m * D_MODEL + n) =
                    make_float2(v0, v1);
                *reinterpret_cast<float2*>(Cout + (size_t)(m + 8) * D_MODEL + n) =
                    make_float2(v2, v3);
            } else {
                const int b = m >> 11;
                const int s = m & 2047;
                const int f = n & 1023;
                const int h = f >> 6;
                const int d = f & 63;
                __nv_bfloat16 h0, h1, h2, h3, l0, l1, l2, l3;
                split2(v0, h0, l0); split2(v1, h1, l1);
                split2(v2, h2, l2); split2(v3, h3, l3);
                if (sect == 0 || sect == 1) {
                    __nv_bfloat16* dh = (sect == 0) ? g_qh : g_kh;
                    __nv_bfloat16* dl = (sect == 0) ? g_ql : g_kl;
                    const size_t o =
                        (((size_t)b * NHEAD + h) * SEQ + s) * HDIM + d;
                    *reinterpret_cast<uint32_t*>(dh + o) = pack_bf(h0, h1);
                    *reinterpret_cast<uint32_t*>(dl + o) = pack_bf(l0, l1);
                    *reinterpret_cast<uint32_t*>(dh + o + 8 * HDIM) = pack_bf(h2, h3);
                    *reinterpret_cast<uint32_t*>(dl + o + 8 * HDIM) = pack_bf(l2, l3);
                } else {
                    const size_t o =
                        (((size_t)b * NHEAD + h) * HDIM + d) * SEQ + s;
                    g_vth[o]            = h0; g_vtl[o]            = l0;
                    g_vth[o + SEQ]      = h1; g_vtl[o + SEQ]      = l1;
                    g_vth[o + 8]        = h2; g_vtl[o + 8]        = l2;
                    g_vth[o + SEQ + 8]  = h3; g_vtl[o + SEQ + 8]  = l3;
                }
            }
        }
    }
}

// ===========================================================================
// Flash attention via HMMA (bf16x3 split), FA2 register-resident P.
// Grid (S/128, H, B), 256 thr = 8 warps, each warp owns 16 q rows x 128 kv.
// KV tiles double-buffered with cp.async; fragments via ldmatrix.x4.
// Per stage: Kh/Kl [128 rows x 144B], Vth/Vtl [64 rows x 272B].
// ===========================================================================
#define FKH 0
#define FKL 18432
#define FVH 36864
#define FVL 54272
#define FST 71680               // stage stride
#define FLASH_SMEM 143360       // 2 stages

__global__ __launch_bounds__(256, 1) void flash_hmma_kernel()
{
    extern __shared__ char fsm[];
    const uint32_t smb = smem_u32(fsm);

    const int tid  = threadIdx.x;
    const int lane = tid & 31;
    const int wid  = tid >> 5;
    const int g    = lane >> 2;
    const int tg   = lane & 3;
    const int qt   = blockIdx.x;
    const int h    = blockIdx.y;
    const int b    = blockIdx.z;
    const int s0   = qt * 128;

    const size_t khead = ((size_t)b * NHEAD + h) * SEQ * HDIM;
    const size_t vhead = ((size_t)b * NHEAD + h) * HDIM * SEQ;

    const int rk  = tid >> 3;       // 0..31 (K rows)
    const int chk = tid & 7;        // 16B chunk (K rows: 128B)
    const int rv  = tid >> 4;       // 0..15 (V rows)
    const int chv = tid & 15;       // 16B chunk (V rows: 256B)

    // ldmatrix B-operand lane mapping
    const int nrowB = (lane & 7) | (((lane >> 4) & 1) << 3);
    const int khB   = ((lane >> 3) & 1) * 16;

    auto load_kv = [&](int kt, int buf) {
        const uint32_t sb = smb + buf * FST;
        const __nv_bfloat16* ksh = g_kh + khead + (size_t)(kt * 128) * HDIM;
        const __nv_bfloat16* ksl = g_kl + khead + (size_t)(kt * 128) * HDIM;
        const __nv_bfloat16* vsh = g_vth + vhead + kt * 128;
        const __nv_bfloat16* vsl = g_vtl + vhead + kt * 128;
#pragma unroll
        for (int j = 0; j < 4; j++) {
            const int r = rk + 32 * j;          // 0..127
            cp16(sb + FKH + (uint32_t)r * 144 + chk * 16,
                 ksh + (size_t)r * HDIM + chk * 8);
            cp16(sb + FKL + (uint32_t)r * 144 + chk * 16,
                 ksl + (size_t)r * HDIM + chk * 8);
        }
#pragma unroll
        for (int j = 0; j < 4; j++) {
            const int r = rv + 16 * j;          // 0..63
            cp16(sb + FVH + (uint32_t)r * 272 + chv * 16,
                 vsh + (size_t)r * SEQ + chv * 8);
            cp16(sb + FVL + (uint32_t)r * 272 + chv * 16,
                 vsl + (size_t)r * SEQ + chv * 8);
        }
    };

    // ---- Q fragments (persistent): rows s0+wid*16+g / +8, k = hd ----
    uint32_t qfh[4][4], qfl[4][4];
    {
        const size_t r0 = khead + (size_t)(s0 + wid * 16 + g) * HDIM;
        const size_t r1 = r0 + 8 * HDIM;
#pragma unroll
        for (int ks = 0; ks < 4; ks++) {
            const int kc = ks * 16 + 2 * tg;
            qfh[ks][0] = *reinterpret_cast<const uint32_t*>(g_qh + r0 + kc);
            qfh[ks][1] = *reinterpret_cast<const uint32_t*>(g_qh + r1 + kc);
            qfh[ks][2] = *reinterpret_cast<const uint32_t*>(g_qh + r0 + kc + 8);
            qfh[ks][3] = *reinterpret_cast<const uint32_t*>(g_qh + r1 + kc + 8);
            qfl[ks][0] = *reinterpret_cast<const uint32_t*>(g_ql + r0 + kc);
            qfl[ks][1] = *reinterpret_cast<const uint32_t*>(g_ql + r1 + kc);
            qfl[ks][2] = *reinterpret_cast<const uint32_t*>(g_ql + r0 + kc + 8);
            qfl[ks][3] = *reinterpret_cast<const uint32_t*>(g_ql + r1 + kc + 8);
        }
    }

    float o[8][4];
    float mi[2] = {-INFINITY, -INFINITY};
    float li[2] = {0.f, 0.f};
#pragma unroll
    for (int nf = 0; nf < 8; nf++)
#pragma unroll
        for (int t = 0; t < 4; t++) o[nf][t] = 0.f;

    load_kv(0, 0);
    CP_COMMIT;

    for (int kt = 0; kt < SEQ / 128; kt++) {
        const int buf = kt & 1;
        if (kt + 1 < SEQ / 128) {
            load_kv(kt + 1, buf ^ 1);   // prefetch next tile
            CP_COMMIT;
            CP_WAIT(1);                 // current tile resident
        } else {
            CP_WAIT(0);
        }
        __syncthreads();

        const uint32_t kb_h = smb + buf * FST + FKH;
        const uint32_t kb_l = smb + buf * FST + FKL;
        const uint32_t vb_h = smb + buf * FST + FVH;
        const uint32_t vb_l = smb + buf * FST + FVL;

        // ---- scores: 16 x 128, per-thread 16 n-frags x 4 ----
        float sc[16][4];
#pragma unroll
        for (int nf = 0; nf < 16; nf++)
#pragma unroll
            for (int t = 0; t < 4; t++) sc[nf][t] = 0.f;

#pragma unroll
        for (int ks = 0; ks < 4; ks++) {
#pragma unroll
            for (int j = 0; j < 8; j++) {      // nf pair (2j, 2j+1)
                uint32_t kh[4], kl[4];
                const uint32_t ko =
                    (uint32_t)(j * 16 + nrowB) * 144 + ks * 32 + khB;
                ldsm4(kh, kb_h + ko);
                ldsm4(kl, kb_l + ko);
                mma_bf16(sc[2 * j],     qfh[ks], kh[0], kh[1]);
                mma_bf16(sc[2 * j],     qfl[ks], kh[0], kh[1]);
                mma_bf16(sc[2 * j],     qfh[ks], kl[0], kl[1]);
                mma_bf16(sc[2 * j + 1], qfh[ks], kh[2], kh[3]);
                mma_bf16(sc[2 * j + 1], qfl[ks], kh[2], kh[3]);
                mma_bf16(sc[2 * j + 1], qfh[ks], kl[2], kl[3]);
            }
        }

        // ---- online softmax ----
        float rmax[2] = {-INFINITY, -INFINITY};
#pragma unroll
        for (int nf = 0; nf < 16; nf++) {
#pragma unroll
            for (int t = 0; t < 4; t++) sc[nf][t] *= 0.125f;
            rmax[0] = fmaxf(rmax[0], fmaxf(sc[nf][0], sc[nf][1]));
            rmax[1] = fmaxf(rmax[1], fmaxf(sc[nf][2], sc[nf][3]));
        }
#pragma unroll
        for (int r = 0; r < 2; r++) {
            rmax[r] = fmaxf(rmax[r], __shfl_xor_sync(0xffffffffu, rmax[r], 1));
            rmax[r] = fmaxf(rmax[r], __shfl_xor_sync(0xffffffffu, rmax[r], 2));
        }
        float mnew[2], corr[2];
#pragma unroll
        for (int r = 0; r < 2; r++) {
            mnew[r] = fmaxf(mi[r], rmax[r]);
            corr[r] = __expf(mi[r] - mnew[r]);
            mi[r] = mnew[r];
        }
#pragma unroll
        for (int nf = 0; nf < 8; nf++) {
            o[nf][0] *= corr[0]; o[nf][1] *= corr[0];
            o[nf][2] *= corr[1]; o[nf][3] *= corr[1];
        }

        float rsum[2] = {0.f, 0.f};
        // ---- P (registers) + PV, per k16 step kk ----
#pragma unroll
        for (int kk = 0; kk < 8; kk++) {
            uint32_t pfh[4], pfl[4];
#pragma unroll
            for (int half = 0; half < 2; half++) {
                const int nf = 2 * kk + half;
                const float p0 = __expf(sc[nf][0] - mnew[0]);
                const float p1 = __expf(sc[nf][1] - mnew[0]);
                const float p2 = __expf(sc[nf][2] - mnew[1]);
                const float p3 = __expf(sc[nf][3] - mnew[1]);
                rsum[0] += p0 + p1;
                rsum[1] += p2 + p3;
                __nv_bfloat16 h0, h1, h2, h3, l0, l1, l2, l3;
                split2(p0, h0, l0); split2(p1, h1, l1);
                split2(p2, h2, l2); split2(p3, h3, l3);
                pfh[0 + 2 * half] = pack_bf(h0, h1);
                pfh[1 + 2 * half] = pack_bf(h2, h3);
                pfl[0 + 2 * half] = pack_bf(l0, l1);
                pfl[1 + 2 * half] = pack_bf(l2, l3);
            }
#pragma unroll
            for (int j = 0; j < 4; j++) {      // nf pair (2j, 2j+1)
                uint32_t vh[4], vl[4];
                const uint32_t vo =
                    (uint32_t)(j * 16 + nrowB) * 272 + kk * 32 + khB;
                ldsm4(vh, vb_h + vo);
                ldsm4(vl, vb_l + vo);
                mma_bf16(o[2 * j],     pfh, vh[0], vh[1]);
                mma_bf16(o[2 * j],     pfl, vh[0], vh[1]);
                mma_bf16(o[2 * j],     pfh, vl[0], vl[1]);
                mma_bf16(o[2 * j + 1], pfh, vh[2], vh[3]);
                mma_bf16(o[2 * j + 1], pfl, vh[2], vh[3]);
                mma_bf16(o[2 * j + 1], pfh, vl[2], vl[3]);
            }
        }
#pragma unroll
        for (int r = 0; r < 2; r++) {
            rsum[r] += __shfl_xor_sync(0xffffffffu, rsum[r], 1);
            rsum[r] += __shfl_xor_sync(0xffffffffu, rsum[r], 2);
            li[r] = li[r] * corr[r] + rsum[r];
        }
        __syncthreads();   // all reads of buf done before kt+2 load overwrites
    }

    // ---- epilogue: write attn hi/lo [8192][1024] ----
    const float inv0 = 1.0f / li[0];
    const float inv1 = 1.0f / li[1];
    const int row0 = b * SEQ + s0 + wid * 16 + g;
    const int row1 = row0 + 8;
#pragma unroll
    for (int nf = 0; nf < 8; nf++) {
        const int col = h * HDIM + nf * 8 + 2 * tg;
        __nv_bfloat16 h0, h1, h2, h3, l0, l1, l2, l3;
        split2(o[nf][0] * inv0, h0, l0);
        split2(o[nf][1] * inv0, h1, l1);
        split2(o[nf][2] * inv1, h2, l2);
        split2(o[nf][3] * inv1, h3, l3);
        *reinterpret_cast<uint32_t*>(g_ah + (size_t)row0 * D_MODEL + col) = pack_bf(h0, h1);
        *reinterpret_cast<uint32_t*>(g_al + (size_t)row0 * D_MODEL + col) = pack_bf(l0, l1);
        *reinterpret_cast<uint32_t*>(g_ah + (size_t)row1 * D_MODEL + col) = pack_bf(h2, h3);
        *reinterpret_cast<uint32_t*>(g_al + (size_t)row1 * D_MODEL + col) = pack_bf(l2, l3);
    }
}

// ===========================================================================
// Launch
// ===========================================================================
extern "C" void kernel_launch(void* const* d_in, const int* in_sizes, int n_in,
                              void* d_out, int out_size)
{
    (void)in_sizes; (void)n_in; (void)out_size;
    const float* x      = (const float*)d_in[0];  // [4,2048,1024]
    const float* W_qkv  = (const float*)d_in[1];  // [3072,1024]
    const float* b_qkv  = (const float*)d_in[2];  // [3072]
    const float* W_proj = (const float*)d_in[3];  // [1024,1024]
    const float* b_proj = (const float*)d_in[4];  // [1024]
    float* out = (float*)d_out;

    cudaFuncSetAttribute(gemm_hmma_kernel,
                         cudaFuncAttributeMaxDynamicSharedMemorySize, GEMM_SMEM);
    cudaFuncSetAttribute(flash_hmma_kernel,
                         cudaFuncAttributeMaxDynamicSharedMemorySize, FLASH_SMEM);

    // resolve device-global addresses (host-side, capture-safe)
    __nv_bfloat16 *xh, *xl, *wqh, *wql, *wph, *wpl;
    cudaGetSymbolAddress((void**)&xh,  g_xh);
    cudaGetSymbolAddress((void**)&xl,  g_xl);
    cudaGetSymbolAddress((void**)&wqh, g_wqh);
    cudaGetSymbolAddress((void**)&wql, g_wql);
    cudaGetSymbolAddress((void**)&wph, g_wph);
    cudaGetSymbolAddress((void**)&wpl, g_wpl);
    __nv_bfloat16 *ah, *al;
    cudaGetSymbolAddress((void**)&ah, g_ah);
    cudaGetSymbolAddress((void**)&al, g_al);

    // 1) pre-split inputs to bf16 hi/lo
    split_kernel<<<(MTOT * KD / 4 + 255) / 256, 256>>>(x, xh, xl, MTOT * KD / 4);
    split_kernel<<<(3 * D_MODEL * KD / 4 + 255) / 256, 256>>>(W_qkv, wqh, wql,
                                                              3 * D_MODEL * KD / 4);
    split_kernel<<<(D_MODEL * KD / 4 + 255) / 256, 256>>>(W_proj, wph, wpl,
                                                          D_MODEL * KD / 4);

    // 2) QKV GEMM -> q/k bf16 h/l + v transposed bf16 h/l
    gemm_hmma_kernel<<<dim3(3 * D_MODEL / 128, MTOT / 128), 128, GEMM_SMEM>>>(
        xh, xl, wqh, wql, b_qkv, nullptr, 0);

    // 3) flash attention -> attn bf16 h/l
    flash_hmma_kernel<<<dim3(SEQ / 128, NHEAD, BATCH), 256, FLASH_SMEM>>>();

    // 4) projection -> out fp32
    gemm_hmma_kernel<<<dim3(D_MODEL / 128, MTOT / 128), 128, GEMM_SMEM>>>(
        ah, al, wph, wpl, b_proj, out, 1);
}

// round 9
// speedup vs baseline: 2.8554x; 1.0030x over previous
#include <cuda_runtime.h>
#include <cuda_bf16.h>
#include <math.h>
#include <stdint.h>

// Problem constants
#define D_MODEL 1024
#define NHEAD   16
#define HDIM    64
#define BATCH   4
#define SEQ     2048
#define MTOT    (BATCH * SEQ)   // 8192
#define KD      1024

// -------- bf16 hi/lo scratch (static device globals; no allocation) --------
__device__ __nv_bfloat16 g_xh[(size_t)MTOT * KD];
__device__ __nv_bfloat16 g_xl[(size_t)MTOT * KD];
__device__ __nv_bfloat16 g_wqh[(size_t)3 * D_MODEL * KD];
__device__ __nv_bfloat16 g_wql[(size_t)3 * D_MODEL * KD];
__device__ __nv_bfloat16 g_wph[(size_t)D_MODEL * KD];
__device__ __nv_bfloat16 g_wpl[(size_t)D_MODEL * KD];
__device__ __nv_bfloat16 g_qh[(size_t)BATCH * NHEAD * SEQ * HDIM]; // [B,H,S,64]
__device__ __nv_bfloat16 g_ql[(size_t)BATCH * NHEAD * SEQ * HDIM];
__device__ __nv_bfloat16 g_kh[(size_t)BATCH * NHEAD * SEQ * HDIM];
__device__ __nv_bfloat16 g_kl[(size_t)BATCH * NHEAD * SEQ * HDIM];
__device__ __nv_bfloat16 g_vth[(size_t)BATCH * NHEAD * HDIM * SEQ]; // [B,H,64,S]
__device__ __nv_bfloat16 g_vtl[(size_t)BATCH * NHEAD * HDIM * SEQ];
__device__ __nv_bfloat16 g_ah[(size_t)MTOT * D_MODEL];               // attn hi
__device__ __nv_bfloat16 g_al[(size_t)MTOT * D_MODEL];               // attn lo

// ===========================================================================
// Helpers
// ===========================================================================
__device__ __forceinline__ uint32_t smem_u32(const void* p) {
    uint32_t a;
    asm("{ .reg .u64 t; cvta.to.shared.u64 t, %1; cvt.u32.u64 %0, t; }"
        : "=r"(a) : "l"(p));
    return a;
}
__device__ __forceinline__ void cp16(uint32_t dst, const void* src) {
    asm volatile("cp.async.cg.shared.global [%0], [%1], 16;"
                 :: "r"(dst), "l"(src));
}
#define CP_COMMIT  asm volatile("cp.async.commit_group;")
#define CP_WAIT(n) asm volatile("cp.async.wait_group %0;" :: "n"(n))

__device__ __forceinline__ void mma_bf16(float* d, const uint32_t* a,
                                         uint32_t b0, uint32_t b1) {
    asm volatile(
        "mma.sync.aligned.m16n8k16.row.col.f32.bf16.bf16.f32 "
        "{%0,%1,%2,%3}, {%4,%5,%6,%7}, {%8,%9}, {%0,%1,%2,%3};"
        : "+f"(d[0]), "+f"(d[1]), "+f"(d[2]), "+f"(d[3])
        : "r"(a[0]), "r"(a[1]), "r"(a[2]), "r"(a[3]), "r"(b0), "r"(b1));
}
__device__ __forceinline__ void ldsm4(uint32_t* r, uint32_t addr) {
    asm volatile("ldmatrix.sync.aligned.m8n8.x4.shared.b16 {%0,%1,%2,%3}, [%4];"
        : "=r"(r[0]), "=r"(r[1]), "=r"(r[2]), "=r"(r[3]) : "r"(addr));
}

__device__ __forceinline__ uint32_t pack_bf(__nv_bfloat16 a, __nv_bfloat16 b) {
    __nv_bfloat162 t; t.x = a; t.y = b;
    return *reinterpret_cast<uint32_t*>(&t);
}
__device__ __forceinline__ void split2(float v, __nv_bfloat16& h, __nv_bfloat16& l) {
    h = __float2bfloat16(v);
    l = __float2bfloat16(v - __bfloat162float(h));
}

// ===========================================================================
// Pre-split: fp32 -> bf16 hi + bf16 lo
// ===========================================================================
__global__ __launch_bounds__(256) void split_kernel(
    const float* __restrict__ src, __nv_bfloat16* __restrict__ hi,
    __nv_bfloat16* __restrict__ lo, int n4)
{
    int i = blockIdx.x * 256 + threadIdx.x;
    if (i >= n4) return;
    float4 v = reinterpret_cast<const float4*>(src)[i];
    __nv_bfloat16 h0, h1, h2, h3, l0, l1, l2, l3;
    split2(v.x, h0, l0); split2(v.y, h1, l1);
    split2(v.z, h2, l2); split2(v.w, h3, l3);
    reinterpret_cast<uint2*>(hi)[i] = make_uint2(pack_bf(h0, h1), pack_bf(h2, h3));
    reinterpret_cast<uint2*>(lo)[i] = make_uint2(pack_bf(l0, l1), pack_bf(l2, l3));
}

// ===========================================================================
// HMMA GEMM: C[m,n] = sum_k A[m,k]*W[n,k] (+bias), bf16x3 split.
// CTA tile 128x128 (128 threads, 4 warps), BK=32, cp.async double buffer.
// Warps: wm = wid&1 (m 64), wn = wid>>1 (n 64). Warp tile 64x64.
// Fragments via ldmatrix.x4. 2 CTAs/SM.
// MMA issue is term-major (mf inner) so same-accumulator reuse distance = 8.
// mode 0: epilogue scatter q/k (bf16 h/l) + v transposed (bf16 h/l).
// mode 1: fp32 + bias -> Cout row-major.
// ===========================================================================
#define GA_H 0                // A hi: 128 rows x 80B
#define GA_L 10240            // A lo
#define GB_H 20480            // B hi: 128 rows x 80B
#define GB_L 30720            // B lo
#define GBUF 40960            // per-stage stride
#define GEMM_SMEM 81920

__global__ __launch_bounds__(128, 2) void gemm_hmma_kernel(
    const __nv_bfloat16* __restrict__ Ah, const __nv_bfloat16* __restrict__ Al,
    const __nv_bfloat16* __restrict__ Wh, const __nv_bfloat16* __restrict__ Wl,
    const float* __restrict__ bias, float* __restrict__ Cout, int mode)
{
    extern __shared__ char gsm[];
    const uint32_t smb = smem_u32(gsm);

    const int tid  = threadIdx.x;
    const int lane = tid & 31;
    const int wid  = tid >> 5;
    const int wm   = wid & 1;
    const int wn   = wid >> 1;
    const int g    = lane >> 2;
    const int tg   = lane & 3;
    const int m0   = blockIdx.y * 128;
    const int n0   = blockIdx.x * 128;

    // ldmatrix lane-address components
    const int mrowA = (lane & 7) | (((lane >> 3) & 1) << 3);
    const int khA   = ((lane >> 4) & 1) * 16;
    const int nrowB = (lane & 7) | (((lane >> 4) & 1) << 3);
    const int khB   = ((lane >> 3) & 1) * 16;

    auto fill = [&](int buf, int c) {
        const __nv_bfloat16* sA_h = Ah + (size_t)m0 * KD + c * 32;
        const __nv_bfloat16* sA_l = Al + (size_t)m0 * KD + c * 32;
        const __nv_bfloat16* sW_h = Wh + (size_t)n0 * KD + c * 32;
        const __nv_bfloat16* sW_l = Wl + (size_t)n0 * KD + c * 32;
        const uint32_t db = smb + buf * GBUF;
#pragma unroll
        for (int i = 0; i < 4; i++) {
            const int idx = tid + i * 128;      // 0..511
            const int row = idx >> 2;
            const int ch  = idx & 3;
            const uint32_t doff = (uint32_t)row * 80 + ch * 16;
            const size_t soff = (size_t)row * KD + ch * 8;
            cp16(db + GA_H + doff, sA_h + soff);
            cp16(db + GA_L + doff, sA_l + soff);
            cp16(db + GB_H + doff, sW_h + soff);
            cp16(db + GB_L + doff, sW_l + soff);
        }
    };

    float acc[4][8][4];
#pragma unroll
    for (int i = 0; i < 4; i++)
#pragma unroll
        for (int j = 0; j < 8; j++)
#pragma unroll
            for (int t = 0; t < 4; t++) acc[i][j][t] = 0.f;

    fill(0, 0);
    CP_COMMIT;

    for (int c = 0; c < KD / 32; c++) {
        const int buf = c & 1;
        if (c + 1 < KD / 32) {
            fill(buf ^ 1, c + 1);
            CP_COMMIT;
            CP_WAIT(1);
        } else {
            CP_WAIT(0);
        }
        __syncthreads();

        const uint32_t db = smb + buf * GBUF;

#pragma unroll
        for (int ks = 0; ks < 2; ks++) {
            uint32_t afh[4][4], afl[4][4];
#pragma unroll
            for (int mf = 0; mf < 4; mf++) {
                const uint32_t ao =
                    (uint32_t)(wm * 64 + mf * 16 + mrowA) * 80 + ks * 32 + khA;
                ldsm4(afh[mf], db + GA_H + ao);
                ldsm4(afl[mf], db + GA_L + ao);
            }
#pragma unroll
            for (int j = 0; j < 4; j++) {       // nf pair (2j, 2j+1)
                uint32_t bh[4], bl[4];
                const uint32_t bo =
                    (uint32_t)(wn * 64 + j * 16 + nrowB) * 80 + ks * 32 + khB;
                ldsm4(bh, db + GB_H + bo);
                ldsm4(bl, db + GB_L + bo);
                // term-major issue: same-acc reuse distance = 8 MMAs
#pragma unroll
                for (int mf = 0; mf < 4; mf++)
                    mma_bf16(acc[mf][2 * j],     afh[mf], bh[0], bh[1]);
#pragma unroll
                for (int mf = 0; mf < 4; mf++)
                    mma_bf16(acc[mf][2 * j + 1], afh[mf], bh[2], bh[3]);
#pragma unroll
                for (int mf = 0; mf < 4; mf++)
                    mma_bf16(acc[mf][2 * j],     afl[mf], bh[0], bh[1]);
#pragma unroll
                for (int mf = 0; mf < 4; mf++)
                    mma_bf16(acc[mf][2 * j + 1], afl[mf], bh[2], bh[3]);
#pragma unroll
                for (int mf = 0; mf < 4; mf++)
                    mma_bf16(acc[mf][2 * j],     afh[mf], bl[0], bl[1]);
#pragma unroll
                for (int mf = 0; mf < 4; mf++)
                    mma_bf16(acc[mf][2 * j + 1], afh[mf], bl[2], bl[3]);
            }
        }
        __syncthreads();
    }

    // ---------------- epilogue ----------------
    const int sect = n0 >> 10;       // 0=q 1=k 2=v (mode 0)
#pragma unroll
    for (int mf = 0; mf < 4; mf++) {
        const int m = m0 + wm * 64 + mf * 16 + g;     // rows m, m+8
#pragma unroll
        for (int nf = 0; nf < 8; nf++) {
            const int n = n0 + wn * 64 + nf * 8 + 2 * tg;
            const float2 bv = *reinterpret_cast<const float2*>(bias + n);
            const float v0 = acc[mf][nf][0] + bv.x;
            const float v1 = acc[mf][nf][1] + bv.y;
            const float v2 = acc[mf][nf][2] + bv.x;
            const float v3 = acc[mf][nf][3] + bv.y;
            if (mode == 1) {
                *reinterpret_cast<float2*>(Cout + (size_t)m * D_MODEL + n) =
                    make_float2(v0, v1);
                *reinterpret_cast<float2*>(Cout + (size_t)(m + 8) * D_MODEL + n) =
                    make_float2(v2, v3);
            } else {
                const int b = m >> 11;
                const int s = m & 2047;
                const int f = n & 1023;
                const int h = f >> 6;
                const int d = f & 63;
                __nv_bfloat16 h0, h1, h2, h3, l0, l1, l2, l3;
                split2(v0, h0, l0); split2(v1, h1, l1);
                split2(v2, h2, l2); split2(v3, h3, l3);
                if (sect == 0 || sect == 1) {
                    __nv_bfloat16* dh = (sect == 0) ? g_qh : g_kh;
                    __nv_bfloat16* dl = (sect == 0) ? g_ql : g_kl;
                    const size_t o =
                        (((size_t)b * NHEAD + h) * SEQ + s) * HDIM + d;
                    *reinterpret_cast<uint32_t*>(dh + o) = pack_bf(h0, h1);
                    *reinterpret_cast<uint32_t*>(dl + o) = pack_bf(l0, l1);
                    *reinterpret_cast<uint32_t*>(dh + o + 8 * HDIM) = pack_bf(h2, h3);
                    *reinterpret_cast<uint32_t*>(dl + o + 8 * HDIM) = pack_bf(l2, l3);
                } else {
                    const size_t o =
                        (((size_t)b * NHEAD + h) * HDIM + d) * SEQ + s;
                    g_vth[o]            = h0; g_vtl[o]            = l0;
                    g_vth[o + SEQ]      = h1; g_vtl[o + SEQ]      = l1;
                    g_vth[o + 8]        = h2; g_vtl[o + 8]        = l2;
                    g_vth[o + SEQ + 8]  = h3; g_vtl[o + SEQ + 8]  = l3;
                }
            }
        }
    }
}

// ===========================================================================
// Flash attention via HMMA (bf16x3 split), FA2 register-resident P.
// Grid (S/128, H, B), 256 thr = 8 warps, each warp owns 16 q rows x 128 kv.
// KV tiles double-buffered with cp.async; fragments via ldmatrix.x4.
// QK and PV loops process j in PAIRS with term-major MMA issue so the
// same-accumulator reuse distance is 4 (vs 1 before).
// Per stage: Kh/Kl [128 rows x 144B], Vth/Vtl [64 rows x 272B].
// ===========================================================================
#define FKH 0
#define FKL 18432
#define FVH 36864
#define FVL 54272
#define FST 71680               // stage stride
#define FLASH_SMEM 143360       // 2 stages

__global__ __launch_bounds__(256, 1) void flash_hmma_kernel()
{
    extern __shared__ char fsm[];
    const uint32_t smb = smem_u32(fsm);

    const int tid  = threadIdx.x;
    const int lane = tid & 31;
    const int wid  = tid >> 5;
    const int g    = lane >> 2;
    const int tg   = lane & 3;
    const int qt   = blockIdx.x;
    const int h    = blockIdx.y;
    const int b    = blockIdx.z;
    const int s0   = qt * 128;

    const size_t khead = ((size_t)b * NHEAD + h) * SEQ * HDIM;
    const size_t vhead = ((size_t)b * NHEAD + h) * HDIM * SEQ;

    const int rk  = tid >> 3;       // 0..31 (K rows)
    const int chk = tid & 7;        // 16B chunk (K rows: 128B)
    const int rv  = tid >> 4;       // 0..15 (V rows)
    const int chv = tid & 15;       // 16B chunk (V rows: 256B)

    const int nrowB = (lane & 7) | (((lane >> 4) & 1) << 3);
    const int khB   = ((lane >> 3) & 1) * 16;

    auto load_kv = [&](int kt, int buf) {
        const uint32_t sb = smb + buf * FST;
        const __nv_bfloat16* ksh = g_kh + khead + (size_t)(kt * 128) * HDIM;
        const __nv_bfloat16* ksl = g_kl + khead + (size_t)(kt * 128) * HDIM;
        const __nv_bfloat16* vsh = g_vth + vhead + kt * 128;
        const __nv_bfloat16* vsl = g_vtl + vhead + kt * 128;
#pragma unroll
        for (int j = 0; j < 4; j++) {
            const int r = rk + 32 * j;          // 0..127
            cp16(sb + FKH + (uint32_t)r * 144 + chk * 16,
                 ksh + (size_t)r * HDIM + chk * 8);
            cp16(sb + FKL + (uint32_t)r * 144 + chk * 16,
                 ksl + (size_t)r * HDIM + chk * 8);
        }
#pragma unroll
        for (int j = 0; j < 4; j++) {
            const int r = rv + 16 * j;          // 0..63
            cp16(sb + FVH + (uint32_t)r * 272 + chv * 16,
                 vsh + (size_t)r * SEQ + chv * 8);
            cp16(sb + FVL + (uint32_t)r * 272 + chv * 16,
                 vsl + (size_t)r * SEQ + chv * 8);
        }
    };

    // ---- Q fragments (persistent): rows s0+wid*16+g / +8, k = hd ----
    uint32_t qfh[4][4], qfl[4][4];
    {
        const size_t r0 = khead + (size_t)(s0 + wid * 16 + g) * HDIM;
        const size_t r1 = r0 + 8 * HDIM;
#pragma unroll
        for (int ks = 0; ks < 4; ks++) {
            const int kc = ks * 16 + 2 * tg;
            qfh[ks][0] = *reinterpret_cast<const uint32_t*>(g_qh + r0 + kc);
            qfh[ks][1] = *reinterpret_cast<const uint32_t*>(g_qh + r1 + kc);
            qfh[ks][2] = *reinterpret_cast<const uint32_t*>(g_qh + r0 + kc + 8);
            qfh[ks][3] = *reinterpret_cast<const uint32_t*>(g_qh + r1 + kc + 8);
            qfl[ks][0] = *reinterpret_cast<const uint32_t*>(g_ql + r0 + kc);
            qfl[ks][1] = *reinterpret_cast<const uint32_t*>(g_ql + r1 + kc);
            qfl[ks][2] = *reinterpret_cast<const uint32_t*>(g_ql + r0 + kc + 8);
            qfl[ks][3] = *reinterpret_cast<const uint32_t*>(g_ql + r1 + kc + 8);
        }
    }

    float o[8][4];
    float mi[2] = {-INFINITY, -INFINITY};
    float li[2] = {0.f, 0.f};
#pragma unroll
    for (int nf = 0; nf < 8; nf++)
#pragma unroll
        for (int t = 0; t < 4; t++) o[nf][t] = 0.f;

    load_kv(0, 0);
    CP_COMMIT;

    for (int kt = 0; kt < SEQ / 128; kt++) {
        const int buf = kt & 1;
        if (kt + 1 < SEQ / 128) {
            load_kv(kt + 1, buf ^ 1);   // prefetch next tile
            CP_COMMIT;
            CP_WAIT(1);                 // current tile resident
        } else {
            CP_WAIT(0);
        }
        __syncthreads();

        const uint32_t kb_h = smb + buf * FST + FKH;
        const uint32_t kb_l = smb + buf * FST + FKL;
        const uint32_t vb_h = smb + buf * FST + FVH;
        const uint32_t vb_l = smb + buf * FST + FVL;

        // ---- scores: 16 x 128, per-thread 16 n-frags x 4 ----
        float sc[16][4];
#pragma unroll
        for (int nf = 0; nf < 16; nf++)
#pragma unroll
            for (int t = 0; t < 4; t++) sc[nf][t] = 0.f;

#pragma unroll
        for (int ks = 0; ks < 4; ks++) {
#pragma unroll
            for (int j = 0; j < 8; j += 2) {   // pair of nf pairs
                uint32_t kh0[4], kl0[4], kh1[4], kl1[4];
                const uint32_t ko0 =
                    (uint32_t)(j * 16 + nrowB) * 144 + ks * 32 + khB;
                const uint32_t ko1 = ko0 + 16 * 144;
                ldsm4(kh0, kb_h + ko0);
                ldsm4(kl0, kb_l + ko0);
                ldsm4(kh1, kb_h + ko1);
                ldsm4(kl1, kb_l + ko1);
                // term-major across 4 accumulators: reuse distance 4
                mma_bf16(sc[2 * j],     qfh[ks], kh0[0], kh0[1]);
                mma_bf16(sc[2 * j + 1], qfh[ks], kh0[2], kh0[3]);
                mma_bf16(sc[2 * j + 2], qfh[ks], kh1[0], kh1[1]);
                mma_bf16(sc[2 * j + 3], qfh[ks], kh1[2], kh1[3]);
                mma_bf16(sc[2 * j],     qfl[ks], kh0[0], kh0[1]);
                mma_bf16(sc[2 * j + 1], qfl[ks], kh0[2], kh0[3]);
                mma_bf16(sc[2 * j + 2], qfl[ks], kh1[0], kh1[1]);
                mma_bf16(sc[2 * j + 3], qfl[ks], kh1[2], kh1[3]);
                mma_bf16(sc[2 * j],     qfh[ks], kl0[0], kl0[1]);
                mma_bf16(sc[2 * j + 1], qfh[ks], kl0[2], kl0[3]);
                mma_bf16(sc[2 * j + 2], qfh[ks], kl1[0], kl1[1]);
                mma_bf16(sc[2 * j + 3], qfh[ks], kl1[2], kl1[3]);
            }
        }

        // ---- online softmax ----
        float rmax[2] = {-INFINITY, -INFINITY};
#pragma unroll
        for (int nf = 0; nf < 16; nf++) {
#pragma unroll
            for (int t = 0; t < 4; t++) sc[nf][t] *= 0.125f;
            rmax[0] = fmaxf(rmax[0], fmaxf(sc[nf][0], sc[nf][1]));
            rmax[1] = fmaxf(rmax[1], fmaxf(sc[nf][2], sc[nf][3]));
        }
#pragma unroll
        for (int r = 0; r < 2; r++) {
            rmax[r] = fmaxf(rmax[r], __shfl_xor_sync(0xffffffffu, rmax[r], 1));
            rmax[r] = fmaxf(rmax[r], __shfl_xor_sync(0xffffffffu, rmax[r], 2));
        }
        float mnew[2], corr[2];
#pragma unroll
        for (int r = 0; r < 2; r++) {
            mnew[r] = fmaxf(mi[r], rmax[r]);
            corr[r] = __expf(mi[r] - mnew[r]);
            mi[r] = mnew[r];
        }
#pragma unroll
        for (int nf = 0; nf < 8; nf++) {
            o[nf][0] *= corr[0]; o[nf][1] *= corr[0];
            o[nf][2] *= corr[1]; o[nf][3] *= corr[1];
        }

        float rsum[2] = {0.f, 0.f};
        // ---- P (registers) + PV, per k16 step kk ----
#pragma unroll
        for (int kk = 0; kk < 8; kk++) {
            uint32_t pfh[4], pfl[4];
#pragma unroll
            for (int half = 0; half < 2; half++) {
                const int nf = 2 * kk + half;
                const float p0 = __expf(sc[nf][0] - mnew[0]);
                const float p1 = __expf(sc[nf][1] - mnew[0]);
                const float p2 = __expf(sc[nf][2] - mnew[1]);
                const float p3 = __expf(sc[nf][3] - mnew[1]);
                rsum[0] += p0 + p1;
                rsum[1] += p2 + p3;
                __nv_bfloat16 h0, h1, h2, h3, l0, l1, l2, l3;
                split2(p0, h0, l0); split2(p1, h1, l1);
                split2(p2, h2, l2); split2(p3, h3, l3);
                pfh[0 + 2 * half] = pack_bf(h0, h1);
                pfh[1 + 2 * half] = pack_bf(h2, h3);
                pfl[0 + 2 * half] = pack_bf(l0, l1);
                pfl[1 + 2 * half] = pack_bf(l2, l3);
            }
#pragma unroll
            for (int j = 0; j < 4; j += 2) {   // pair of nf pairs
                uint32_t vh0[4], vl0[4], vh1[4], vl1[4];
                const uint32_t vo0 =
                    (uint32_t)(j * 16 + nrowB) * 272 + kk * 32 + khB;
                const uint32_t vo1 = vo0 + 16 * 272;
                ldsm4(vh0, vb_h + vo0);
                ldsm4(vl0, vb_l + vo0);
                ldsm4(vh1, vb_h + vo1);
                ldsm4(vl1, vb_l + vo1);
                // term-major across 4 accumulators: reuse distance 4
                mma_bf16(o[2 * j],     pfh, vh0[0], vh0[1]);
                mma_bf16(o[2 * j + 1], pfh, vh0[2], vh0[3]);
                mma_bf16(o[2 * j + 2], pfh, vh1[0], vh1[1]);
                mma_bf16(o[2 * j + 3], pfh, vh1[2], vh1[3]);
                mma_bf16(o[2 * j],     pfl, vh0[0], vh0[1]);
                mma_bf16(o[2 * j + 1], pfl, vh0[2], vh0[3]);
                mma_bf16(o[2 * j + 2], pfl, vh1[0], vh1[1]);
                mma_bf16(o[2 * j + 3], pfl, vh1[2], vh1[3]);
                mma_bf16(o[2 * j],     pfh, vl0[0], vl0[1]);
                mma_bf16(o[2 * j + 1], pfh, vl0[2], vl0[3]);
                mma_bf16(o[2 * j + 2], pfh, vl1[0], vl1[1]);
                mma_bf16(o[2 * j + 3], pfh, vl1[2], vl1[3]);
            }
        }
#pragma unroll
        for (int r = 0; r < 2; r++) {
            rsum[r] += __shfl_xor_sync(0xffffffffu, rsum[r], 1);
            rsum[r] += __shfl_xor_sync(0xffffffffu, rsum[r], 2);
            li[r] = li[r] * corr[r] + rsum[r];
        }
        __syncthreads();   // all reads of buf done before kt+2 load overwrites
    }

    // ---- epilogue: write attn hi/lo [8192][1024] ----
    const float inv0 = 1.0f / li[0];
    const float inv1 = 1.0f / li[1];
    const int row0 = b * SEQ + s0 + wid * 16 + g;
    const int row1 = row0 + 8;
#pragma unroll
    for (int nf = 0; nf < 8; nf++) {
        const int col = h * HDIM + nf * 8 + 2 * tg;
        __nv_bfloat16 h0, h1, h2, h3, l0, l1, l2, l3;
        split2(o[nf][0] * inv0, h0, l0);
        split2(o[nf][1] * inv0, h1, l1);
        split2(o[nf][2] * inv1, h2, l2);
        split2(o[nf][3] * inv1, h3, l3);
        *reinterpret_cast<uint32_t*>(g_ah + (size_t)row0 * D_MODEL + col) = pack_bf(h0, h1);
        *reinterpret_cast<uint32_t*>(g_al + (size_t)row0 * D_MODEL + col) = pack_bf(l0, l1);
        *reinterpret_cast<uint32_t*>(g_ah + (size_t)row1 * D_MODEL + col) = pack_bf(h2, h3);
        *reinterpret_cast<uint32_t*>(g_al + (size_t)row1 * D_MODEL + col) = pack_bf(l2, l3);
    }
}

// ===========================================================================
// Launch
// ===========================================================================
extern "C" void kernel_launch(void* const* d_in, const int* in_sizes, int n_in,
                              void* d_out, int out_size)
{
    (void)in_sizes; (void)n_in; (void)out_size;
    const float* x      = (const float*)d_in[0];  // [4,2048,1024]
    const float* W_qkv  = (const float*)d_in[1];  // [3072,1024]
    const float* b_qkv  = (const float*)d_in[2];  // [3072]
    const float* W_proj = (const float*)d_in[3];  // [1024,1024]
    const float* b_proj = (const float*)d_in[4];  // [1024]
    float* out = (float*)d_out;

    cudaFuncSetAttribute(gemm_hmma_kernel,
                         cudaFuncAttributeMaxDynamicSharedMemorySize, GEMM_SMEM);
    cudaFuncSetAttribute(flash_hmma_kernel,
                         cudaFuncAttributeMaxDynamicSharedMemorySize, FLASH_SMEM);

    // resolve device-global addresses (host-side, capture-safe)
    __nv_bfloat16 *xh, *xl, *wqh, *wql, *wph, *wpl;
    cudaGetSymbolAddress((void**)&xh,  g_xh);
    cudaGetSymbolAddress((void**)&xl,  g_xl);
    cudaGetSymbolAddress((void**)&wqh, g_wqh);
    cudaGetSymbolAddress((void**)&wql, g_wql);
    cudaGetSymbolAddress((void**)&wph, g_wph);
    cudaGetSymbolAddress((void**)&wpl, g_wpl);
    __nv_bfloat16 *ah, *al;
    cudaGetSymbolAddress((void**)&ah, g_ah);
    cudaGetSymbolAddress((void**)&al, g_al);

    // 1) pre-split inputs to bf16 hi/lo
    split_kernel<<<(MTOT * KD / 4 + 255) / 256, 256>>>(x, xh, xl, MTOT * KD / 4);
    split_kernel<<<(3 * D_MODEL * KD / 4 + 255) / 256, 256>>>(W_qkv, wqh, wql,
                                                              3 * D_MODEL * KD / 4);
    split_kernel<<<(D_MODEL * KD / 4 + 255) / 256, 256>>>(W_proj, wph, wpl,
                                                          D_MODEL * KD / 4);

    // 2) QKV GEMM -> q/k bf16 h/l + v transposed bf16 h/l
    gemm_hmma_kernel<<<dim3(3 * D_MODEL / 128, MTOT / 128), 128, GEMM_SMEM>>>(
        xh, xl, wqh, wql, b_qkv, nullptr, 0);

    // 3) flash attention -> attn bf16 h/l
    flash_hmma_kernel<<<dim3(SEQ / 128, NHEAD, BATCH), 256, FLASH_SMEM>>>();

    // 4) projection -> out fp32
    gemm_hmma_kernel<<<dim3(D_MODEL / 128, MTOT / 128), 128, GEMM_SMEM>>>(
        ah, al, wph, wpl, b_proj, out, 1);
}